// round 12
// baseline (speedup 1.0000x reference)
#include <cuda_runtime.h>
#include <cuda_bf16.h>
#include <math.h>
#include <stdint.h>

// ---------------------------------------------------------------------------
// Model dims (compile-time)
// ---------------------------------------------------------------------------
#define BB 4
#define TT 2048
#define DD 256
#define HH 4
#define HD 64
#define LL 2
#define QQ 128          // MAX_BITS*2 out queries

// ---------------------------------------------------------------------------
// Scratch (device globals; no runtime allocation allowed)
// ---------------------------------------------------------------------------
__device__ float g_x  [BB*TT*DD];        // residual stream
__device__ float g_xn [BB*TT*DD];        // final layernormed activations
__device__ float g_qkv[BB*TT*3*DD];      // qkv projections
__device__ __nv_bfloat16 g_a1h[BB*TT*DD],   g_a1l[BB*TT*DD];     // act split (D)
__device__ __nv_bfloat16 g_a2h[BB*TT*4*DD], g_a2l[BB*TT*4*DD];   // ffn hidden split
__device__ __nv_bfloat16 g_wth[4*DD*DD],    g_wtl[4*DD*DD];      // weight^T split

// ---------------------------------------------------------------------------
// bf16 split helpers + mma + cp.async
// ---------------------------------------------------------------------------
__device__ __forceinline__ void mma_bf16(float* c, const uint32_t* a,
                                         const uint32_t* b) {
    asm volatile(
        "mma.sync.aligned.m16n8k16.row.col.f32.bf16.bf16.f32 "
        "{%0,%1,%2,%3}, {%4,%5,%6,%7}, {%8,%9}, {%0,%1,%2,%3};"
        : "+f"(c[0]), "+f"(c[1]), "+f"(c[2]), "+f"(c[3])
        : "r"(a[0]), "r"(a[1]), "r"(a[2]), "r"(a[3]), "r"(b[0]), "r"(b[1]));
}

__device__ __forceinline__ uint32_t pack2bf(__nv_bfloat16 a, __nv_bfloat16 b) {
    return (uint32_t)__bfloat16_as_ushort(a) |
           ((uint32_t)__bfloat16_as_ushort(b) << 16);
}

__device__ __forceinline__ void split2(float x0, float x1,
                                       uint32_t& h, uint32_t& l) {
    __nv_bfloat16 h0 = __float2bfloat16(x0);
    __nv_bfloat16 h1 = __float2bfloat16(x1);
    __nv_bfloat16 l0 = __float2bfloat16(x0 - __bfloat162float(h0));
    __nv_bfloat16 l1 = __float2bfloat16(x1 - __bfloat162float(h1));
    h = pack2bf(h0, h1);
    l = pack2bf(l0, l1);
}

__device__ __forceinline__ uint32_t smem_u32(const void* p) {
    uint32_t a;
    asm("{ .reg .u64 t; cvta.to.shared.u64 t, %1; cvt.u32.u64 %0, t; }"
        : "=r"(a) : "l"(p));
    return a;
}

__device__ __forceinline__ void cpa16(uint32_t s, const void* g) {
    asm volatile("cp.async.cg.shared.global [%0], [%1], 16;"
                 :: "r"(s), "l"(g));
}
#define CPA_COMMIT() asm volatile("cp.async.commit_group;" ::: "memory")
#define CPA_WAIT0()  asm volatile("cp.async.wait_group 0;" ::: "memory")

// ---------------------------------------------------------------------------
// Reductions
// ---------------------------------------------------------------------------
__device__ __forceinline__ float blockReduceSum256(float v) {
    __shared__ float sh[8];
    int lane = threadIdx.x & 31, wid = threadIdx.x >> 5;
    #pragma unroll
    for (int o = 16; o; o >>= 1) v += __shfl_xor_sync(0xffffffffu, v, o);
    if (lane == 0) sh[wid] = v;
    __syncthreads();
    if (wid == 0) {
        float r = (lane < 8) ? sh[lane] : 0.f;
        #pragma unroll
        for (int o = 4; o; o >>= 1) r += __shfl_xor_sync(0xffffffffu, r, o);
        if (lane == 0) sh[0] = r;
    }
    __syncthreads();
    float r = sh[0];
    __syncthreads();
    return r;
}

__device__ __forceinline__ float blockReduceMax256(float v) {
    __shared__ float sh[8];
    int lane = threadIdx.x & 31, wid = threadIdx.x >> 5;
    #pragma unroll
    for (int o = 16; o; o >>= 1) v = fmaxf(v, __shfl_xor_sync(0xffffffffu, v, o));
    if (lane == 0) sh[wid] = v;
    __syncthreads();
    if (wid == 0) {
        float r = (lane < 8) ? sh[lane] : -1e30f;
        #pragma unroll
        for (int o = 4; o; o >>= 1) r = fmaxf(r, __shfl_xor_sync(0xffffffffu, r, o));
        if (lane == 0) sh[0] = r;
    }
    __syncthreads();
    float r = sh[0];
    __syncthreads();
    return r;
}

// ---------------------------------------------------------------------------
// Embedding lookup
// ---------------------------------------------------------------------------
__global__ void embed_kernel(const int* __restrict__ tokens,
                             const float* __restrict__ embed,
                             float* __restrict__ x) {
    int row = blockIdx.x;
    int d   = threadIdx.x;
    int tok = tokens[row];
    x[(size_t)row * DD + d] = embed[(size_t)tok * DD + d];
}

// ---------------------------------------------------------------------------
// LayerNorm over D=256 -> fp32
// ---------------------------------------------------------------------------
__global__ void ln_kernel(const float* __restrict__ x,
                          const float* __restrict__ w,
                          const float* __restrict__ b,
                          float* __restrict__ y) {
    int row = blockIdx.x;
    int d   = threadIdx.x;
    float v  = x[(size_t)row * DD + d];
    float mu = blockReduceSum256(v) * (1.f / DD);
    float dv = v - mu;
    float var = blockReduceSum256(dv * dv) * (1.f / DD);
    float r = rsqrtf(var + 1e-5f);
    y[(size_t)row * DD + d] = dv * r * w[d] + b[d];
}

// ---------------------------------------------------------------------------
// LayerNorm -> bf16 hi/lo split
// ---------------------------------------------------------------------------
__global__ void ln_split_kernel(const float* __restrict__ x,
                                const float* __restrict__ w,
                                const float* __restrict__ b,
                                __nv_bfloat16* __restrict__ oh,
                                __nv_bfloat16* __restrict__ ol) {
    int row = blockIdx.x;
    int d   = threadIdx.x;
    float v  = x[(size_t)row * DD + d];
    float mu = blockReduceSum256(v) * (1.f / DD);
    float dv = v - mu;
    float var = blockReduceSum256(dv * dv) * (1.f / DD);
    float r = rsqrtf(var + 1e-5f);
    float y = dv * r * w[d] + b[d];
    __nv_bfloat16 h = __float2bfloat16(y);
    size_t i = (size_t)row * DD + d;
    oh[i] = h;
    ol[i] = __float2bfloat16(y - __bfloat162float(h));
}

// ---------------------------------------------------------------------------
// Weight split + transpose: W[K][N] fp32 -> T[N][K] bf16 hi/lo
// ---------------------------------------------------------------------------
__global__ void wsplitT_kernel(const float* __restrict__ W,
                               __nv_bfloat16* __restrict__ Th,
                               __nv_bfloat16* __restrict__ Tl,
                               int K, int N) {
    int idx = blockIdx.x * 256 + threadIdx.x;   // n*K + k
    int n = idx / K, k = idx - n * K;
    float v = W[(size_t)k * N + n];
    __nv_bfloat16 h = __float2bfloat16(v);
    Th[idx] = h;
    Tl[idx] = __float2bfloat16(v - __bfloat162float(h));
}

// ---------------------------------------------------------------------------
// Pre-split bf16 HMMA GEMM, cp.async 2-stage, FAT warp tile 64x64.
// C[M,N] = A[M,K] @ B^T'[N,K] + bias
//   EPI 0: bias -> fp32 C
//   EPI 1: bias+gelu -> bf16 hi/lo (Chi/Clo)
//   EPI 2: bias+residual accumulate -> fp32 C
// CTA 128x128, 4 warps (2x2), warp tile 64x64, BK=32, smem stride 40.
// ---------------------------------------------------------------------------
#define TST 40
#define STAGE_ELEMS (4 * 128 * TST)              // Ah,Al,Bh,Bl per stage
#define GB_SMEM (2 * STAGE_ELEMS * 2)            // bytes

template <int EPI>
__global__ __launch_bounds__(128, 2) void gemm_bf16_kernel(
    const __nv_bfloat16* __restrict__ Ahg, const __nv_bfloat16* __restrict__ Alg,
    const __nv_bfloat16* __restrict__ Bhg, const __nv_bfloat16* __restrict__ Blg,
    const float* __restrict__ bias, float* __restrict__ C,
    __nv_bfloat16* __restrict__ Chi, __nv_bfloat16* __restrict__ Clo,
    int M, int N, int K) {
    extern __shared__ __nv_bfloat16 smb[];
    const uint32_t sbase = smem_u32(smb);

    const int tid  = threadIdx.x;
    const int warp = tid >> 5, lane = tid & 31;
    const int g = lane >> 2, tig = lane & 3;
    const int wm = (warp & 1) * 64, wn = (warp >> 1) * 64;
    const int bm = blockIdx.y * 128, bn = blockIdx.x * 128;

    float acc[4][8][4];
    #pragma unroll
    for (int mf = 0; mf < 4; mf++)
        #pragma unroll
        for (int nf = 0; nf < 8; nf++)
            #pragma unroll
            for (int c = 0; c < 4; c++) acc[mf][nf][c] = 0.f;

    // staging: 128 threads, one full row (64B = 4x16B) per buffer each
    const uint32_t soA = tid * TST;

    auto issue = [&](int st, int k0) {
        uint32_t sb = sbase + (uint32_t)(st * STAGE_ELEMS) * 2;
        const __nv_bfloat16* ga_h = Ahg + (size_t)(bm + tid) * K + k0;
        const __nv_bfloat16* ga_l = Alg + (size_t)(bm + tid) * K + k0;
        const __nv_bfloat16* gb_h = Bhg + (size_t)(bn + tid) * K + k0;
        const __nv_bfloat16* gb_l = Blg + (size_t)(bn + tid) * K + k0;
        #pragma unroll
        for (int q = 0; q < 4; q++) {
            cpa16(sb + (soA + q * 8) * 2,                 ga_h + q * 8);
            cpa16(sb + (128 * TST + soA + q * 8) * 2,     ga_l + q * 8);
            cpa16(sb + (2 * 128 * TST + soA + q * 8) * 2, gb_h + q * 8);
            cpa16(sb + (3 * 128 * TST + soA + q * 8) * 2, gb_l + q * 8);
        }
        CPA_COMMIT();
    };

    const int NT = K >> 5;
    issue(0, 0);

    for (int kt = 0; kt < NT; kt++) {
        CPA_WAIT0();
        __syncthreads();
        if (kt + 1 < NT) issue((kt + 1) & 1, (kt + 1) * 32);

        const __nv_bfloat16* Ah = smb + (kt & 1) * STAGE_ELEMS;
        const __nv_bfloat16* Al = Ah + 128 * TST;
        const __nv_bfloat16* Bh = Al + 128 * TST;
        const __nv_bfloat16* Bl = Bh + 128 * TST;

        #pragma unroll
        for (int ks2 = 0; ks2 < 2; ks2++) {
            const int kb = ks2 * 16;
            uint32_t bhf[8][2], blf[8][2];
            #pragma unroll
            for (int nf = 0; nf < 8; nf++) {
                int n0 = wn + nf * 8 + g;
                uint32_t o0 = n0 * TST + kb + tig * 2;
                bhf[nf][0] = *(const uint32_t*)&Bh[o0];
                bhf[nf][1] = *(const uint32_t*)&Bh[o0 + 8];
                blf[nf][0] = *(const uint32_t*)&Bl[o0];
                blf[nf][1] = *(const uint32_t*)&Bl[o0 + 8];
            }
            #pragma unroll
            for (int mf = 0; mf < 4; mf++) {
                int r0 = wm + mf * 16 + g;
                uint32_t oa = r0 * TST + kb + tig * 2;
                uint32_t ob = (r0 + 8) * TST + kb + tig * 2;
                uint32_t ahf[4], alf[4];
                ahf[0] = *(const uint32_t*)&Ah[oa];
                ahf[1] = *(const uint32_t*)&Ah[ob];
                ahf[2] = *(const uint32_t*)&Ah[oa + 8];
                ahf[3] = *(const uint32_t*)&Ah[ob + 8];
                alf[0] = *(const uint32_t*)&Al[oa];
                alf[1] = *(const uint32_t*)&Al[ob];
                alf[2] = *(const uint32_t*)&Al[oa + 8];
                alf[3] = *(const uint32_t*)&Al[ob + 8];
                #pragma unroll
                for (int nf = 0; nf < 8; nf++) {
                    mma_bf16(acc[mf][nf], ahf, bhf[nf]);
                    mma_bf16(acc[mf][nf], ahf, blf[nf]);
                    mma_bf16(acc[mf][nf], alf, bhf[nf]);
                }
            }
        }
    }

    #pragma unroll
    for (int mf = 0; mf < 4; mf++) {
        #pragma unroll
        for (int nf = 0; nf < 8; nf++) {
            float* cc = acc[mf][nf];
            int r0 = bm + wm + mf * 16 + g;
            int c0 = bn + wn + nf * 8 + tig * 2;
            float bv0 = bias[c0], bv1 = bias[c0 + 1];
            float v0 = cc[0] + bv0, v1 = cc[1] + bv1;
            float v2 = cc[2] + bv0, v3 = cc[3] + bv1;
            if (EPI == 1) {
                v0 = 0.5f * v0 * (1.f + erff(v0 * 0.70710678118654752f));
                v1 = 0.5f * v1 * (1.f + erff(v1 * 0.70710678118654752f));
                v2 = 0.5f * v2 * (1.f + erff(v2 * 0.70710678118654752f));
                v3 = 0.5f * v3 * (1.f + erff(v3 * 0.70710678118654752f));
                uint32_t h, l;
                split2(v0, v1, h, l);
                *(uint32_t*)(Chi + (size_t)r0 * N + c0) = h;
                *(uint32_t*)(Clo + (size_t)r0 * N + c0) = l;
                split2(v2, v3, h, l);
                *(uint32_t*)(Chi + (size_t)(r0 + 8) * N + c0) = h;
                *(uint32_t*)(Clo + (size_t)(r0 + 8) * N + c0) = l;
            } else {
                if (EPI == 2) {
                    float2 o0 = *(const float2*)(C + (size_t)r0 * N + c0);
                    float2 o1 = *(const float2*)(C + (size_t)(r0 + 8) * N + c0);
                    v0 += o0.x; v1 += o0.y; v2 += o1.x; v3 += o1.y;
                }
                float2 s0; s0.x = v0; s0.y = v1;
                float2 s1; s1.x = v2; s1.y = v3;
                *(float2*)(C + (size_t)r0 * N + c0)       = s0;
                *(float2*)(C + (size_t)(r0 + 8) * N + c0) = s1;
            }
        }
    }
}

// ---------------------------------------------------------------------------
// RoPE applied in-place to q and k parts of g_qkv.
// ---------------------------------------------------------------------------
__global__ void rope_kernel(float* __restrict__ qkv) {
    int idx  = blockIdx.x * blockDim.x + threadIdx.x;
    int d    = idx & 31;
    int h    = (idx >> 5) & 3;
    int part = (idx >> 7) & 1;
    int row  = idx >> 8;           // b*T + t
    int t    = row & (TT - 1);
    float inv = powf(10000.f, -(float)d * (1.f / 32.f));
    float ang = (float)t * inv;
    float s, c;
    sincosf(ang, &s, &c);
    float* p = qkv + (size_t)row * (3 * DD) + part * DD + h * HD;
    float x0 = p[d], x1 = p[d + 32];
    p[d]      = x0 * c - x1 * s;
    p[d + 32] = x1 * c + x0 * s;
}

// ---------------------------------------------------------------------------
// Tiled flash attention (fp32 SIMT). One block per (b,h,64-q tile).
// Epilogue writes bf16 hi/lo directly (feeds proj GEMM A operand).
// ---------------------------------------------------------------------------
#define PS_STRIDE 68
#define FATTN_SMEM ((64*64*3 + 64*PS_STRIDE) * 4)

__global__ __launch_bounds__(256) void fattn_kernel(
    const float* __restrict__ qkv,
    __nv_bfloat16* __restrict__ oh, __nv_bfloat16* __restrict__ ol) {
    extern __shared__ float sm[];
    float* Qs = sm;                 // [k][i], stride 64
    float* Ks = sm + 4096;          // [k][j], stride 64
    float* Vs = sm + 8192;          // [s][d], stride 64
    float* Ps = sm + 12288;         // [s][i], stride 68

    int qt = (gridDim.x - 1) - blockIdx.x;
    int h  = blockIdx.y;
    int b  = blockIdx.z;
    int tid = threadIdx.x;
    int tx = tid & 15, ty = tid >> 4;

    int lr = tid >> 2;
    int lc = (tid & 3) * 16;

    const float* base = qkv + (size_t)b * TT * (3 * DD);

    {
        const float* qrow = base + (size_t)(qt * 64 + lr) * (3 * DD) + h * HD + lc;
        #pragma unroll
        for (int m = 0; m < 4; m++) {
            float4 v = *(const float4*)(qrow + m * 4);
            int c = lc + m * 4;
            Qs[(c + 0) * 64 + lr] = v.x * 0.125f;
            Qs[(c + 1) * 64 + lr] = v.y * 0.125f;
            Qs[(c + 2) * 64 + lr] = v.z * 0.125f;
            Qs[(c + 3) * 64 + lr] = v.w * 0.125f;
        }
    }

    float m_i[4], l_i[4], acc[4][4];
    #pragma unroll
    for (int i = 0; i < 4; i++) {
        m_i[i] = -1e30f; l_i[i] = 0.f;
        #pragma unroll
        for (int j = 0; j < 4; j++) acc[i][j] = 0.f;
    }

    for (int kt = 0; kt <= qt; kt++) {
        __syncthreads();
        {
            const float* krow = base + (size_t)(kt * 64 + lr) * (3 * DD) + DD + h * HD + lc;
            #pragma unroll
            for (int m = 0; m < 4; m++) {
                float4 v = *(const float4*)(krow + m * 4);
                int c = lc + m * 4;
                Ks[(c + 0) * 64 + lr] = v.x;
                Ks[(c + 1) * 64 + lr] = v.y;
                Ks[(c + 2) * 64 + lr] = v.z;
                Ks[(c + 3) * 64 + lr] = v.w;
            }
            const float* vrow = base + (size_t)(kt * 64 + lr) * (3 * DD) + 2 * DD + h * HD + lc;
            #pragma unroll
            for (int m = 0; m < 4; m++) {
                *(float4*)&Vs[lr * 64 + lc + m * 4] = *(const float4*)(vrow + m * 4);
            }
        }
        __syncthreads();

        float s[4][4] = {};
        #pragma unroll 4
        for (int k = 0; k < 64; k++) {
            float4 qa = *(const float4*)&Qs[k * 64 + ty * 4];
            float4 kb = *(const float4*)&Ks[k * 64 + tx * 4];
            float ar[4] = {qa.x, qa.y, qa.z, qa.w};
            float br[4] = {kb.x, kb.y, kb.z, kb.w};
            #pragma unroll
            for (int i = 0; i < 4; i++)
                #pragma unroll
                for (int j = 0; j < 4; j++)
                    s[i][j] += ar[i] * br[j];
        }

        if (kt == qt) {
            #pragma unroll
            for (int i = 0; i < 4; i++)
                #pragma unroll
                for (int j = 0; j < 4; j++)
                    if (tx * 4 + j > ty * 4 + i) s[i][j] = -1e30f;
        }

        #pragma unroll
        for (int i = 0; i < 4; i++) {
            float rm = fmaxf(fmaxf(s[i][0], s[i][1]), fmaxf(s[i][2], s[i][3]));
            #pragma unroll
            for (int o = 8; o; o >>= 1) rm = fmaxf(rm, __shfl_xor_sync(0xffffffffu, rm, o));
            float nm = fmaxf(m_i[i], rm);
            float corr = __expf(m_i[i] - nm);
            m_i[i] = nm;
            float rs = 0.f;
            #pragma unroll
            for (int j = 0; j < 4; j++) {
                float p = __expf(s[i][j] - nm);
                Ps[(tx * 4 + j) * PS_STRIDE + ty * 4 + i] = p;
                rs += p;
            }
            #pragma unroll
            for (int o = 8; o; o >>= 1) rs += __shfl_xor_sync(0xffffffffu, rs, o);
            l_i[i] = l_i[i] * corr + rs;
            #pragma unroll
            for (int j = 0; j < 4; j++) acc[i][j] *= corr;
        }
        __syncthreads();

        #pragma unroll 4
        for (int ss = 0; ss < 64; ss++) {
            float4 pa = *(const float4*)&Ps[ss * PS_STRIDE + ty * 4];
            float4 vb = *(const float4*)&Vs[ss * 64 + tx * 4];
            float pr[4] = {pa.x, pa.y, pa.z, pa.w};
            float vr[4] = {vb.x, vb.y, vb.z, vb.w};
            #pragma unroll
            for (int i = 0; i < 4; i++)
                #pragma unroll
                for (int j = 0; j < 4; j++)
                    acc[i][j] += pr[i] * vr[j];
        }
    }

    #pragma unroll
    for (int i = 0; i < 4; i++) {
        float inv = 1.f / l_i[i];
        int t = qt * 64 + ty * 4 + i;
        float v0 = acc[i][0] * inv, v1 = acc[i][1] * inv;
        float v2 = acc[i][2] * inv, v3 = acc[i][3] * inv;
        uint32_t h0, l0, h1, l1;
        split2(v0, v1, h0, l0);
        split2(v2, v3, h1, l1);
        size_t idx = (size_t)(b * TT + t) * DD + h * HD + tx * 4;
        *(uint32_t*)(oh + idx)     = h0;
        *(uint32_t*)(oh + idx + 2) = h1;
        *(uint32_t*)(ol + idx)     = l0;
        *(uint32_t*)(ol + idx + 2) = l1;
    }
}

// ---------------------------------------------------------------------------
// q_scores as GEMM: C[q,t] = (1/16) * queries[q,:].xn[b,t,:]
// ---------------------------------------------------------------------------
__global__ __launch_bounds__(256) void qscore_kernel(
    const float* __restrict__ xn, const float* __restrict__ queries,
    float* __restrict__ qattn) {
    __shared__ float Qs[2][8][128];
    __shared__ float Xs[2][8][64];
    int b  = blockIdx.y;
    int t0 = blockIdx.x * 64;
    int tid = threadIdx.x;
    int tx = tid & 15, ty = tid >> 4;

    int qr = tid >> 1, qc = (tid & 1) * 4;
    int xr = tid >> 1, xc = (tid & 1) * 4;
    bool xact = tid < 128;
    const float* xb = xn + (size_t)b * TT * DD;

    float acc[8][4];
    #pragma unroll
    for (int i = 0; i < 8; i++)
        #pragma unroll
        for (int j = 0; j < 4; j++) acc[i][j] = 0.f;

    {
        float4 qv = *(const float4*)(queries + qr * DD + qc);
        Qs[0][qc + 0][qr] = qv.x; Qs[0][qc + 1][qr] = qv.y;
        Qs[0][qc + 2][qr] = qv.z; Qs[0][qc + 3][qr] = qv.w;
        if (xact) {
            float4 xv = *(const float4*)(xb + (size_t)(t0 + xr) * DD + xc);
            Xs[0][xc + 0][xr] = xv.x; Xs[0][xc + 1][xr] = xv.y;
            Xs[0][xc + 2][xr] = xv.z; Xs[0][xc + 3][xr] = xv.w;
        }
    }
    __syncthreads();

    const int NT = DD >> 3;   // 32
    for (int kt = 0; kt < NT; kt++) {
        int cur = kt & 1;
        float4 qv, xv;
        if (kt + 1 < NT) {
            qv = *(const float4*)(queries + qr * DD + (kt + 1) * 8 + qc);
            if (xact)
                xv = *(const float4*)(xb + (size_t)(t0 + xr) * DD + (kt + 1) * 8 + xc);
        }
        #pragma unroll
        for (int kk = 0; kk < 8; kk++) {
            float a0[8], b0[4];
            *(float4*)&a0[0] = *(const float4*)&Qs[cur][kk][ty * 4];
            *(float4*)&a0[4] = *(const float4*)&Qs[cur][kk][64 + ty * 4];
            *(float4*)&b0[0] = *(const float4*)&Xs[cur][kk][tx * 4];
            #pragma unroll
            for (int i = 0; i < 8; i++)
                #pragma unroll
                for (int j = 0; j < 4; j++)
                    acc[i][j] += a0[i] * b0[j];
        }
        if (kt + 1 < NT) {
            int nxt = cur ^ 1;
            Qs[nxt][qc + 0][qr] = qv.x; Qs[nxt][qc + 1][qr] = qv.y;
            Qs[nxt][qc + 2][qr] = qv.z; Qs[nxt][qc + 3][qr] = qv.w;
            if (xact) {
                Xs[nxt][xc + 0][xr] = xv.x; Xs[nxt][xc + 1][xr] = xv.y;
                Xs[nxt][xc + 2][xr] = xv.z; Xs[nxt][xc + 3][xr] = xv.w;
            }
            __syncthreads();
        }
    }

    #pragma unroll
    for (int i = 0; i < 8; i++) {
        int q = (i < 4) ? ty * 4 + i : 64 + ty * 4 + (i - 4);
        float4 o;
        o.x = acc[i][0] * 0.0625f; o.y = acc[i][1] * 0.0625f;
        o.z = acc[i][2] * 0.0625f; o.w = acc[i][3] * 0.0625f;
        *(float4*)(qattn + (size_t)(b * QQ + q) * TT + t0 + tx * 4) = o;
    }
}

// ---------------------------------------------------------------------------
// Softmax over last dim (2048), in place. One block per row.
// ---------------------------------------------------------------------------
__global__ __launch_bounds__(256) void softmax2048_kernel(float* __restrict__ p) {
    float* row = p + (size_t)blockIdx.x * TT;
    int tid = threadIdx.x;
    float v[8];
    float mx = -1e30f;
    #pragma unroll
    for (int j = 0; j < 8; j++) { v[j] = row[tid + 256 * j]; mx = fmaxf(mx, v[j]); }
    mx = blockReduceMax256(mx);
    float s = 0.f;
    #pragma unroll
    for (int j = 0; j < 8; j++) { v[j] = __expf(v[j] - mx); s += v[j]; }
    s = blockReduceSum256(s);
    float inv = 1.f / s;
    #pragma unroll
    for (int j = 0; j < 8; j++) row[tid + 256 * j] = v[j] * inv;
}

// ---------------------------------------------------------------------------
// selbits: 8 query rows per block share one streaming pass over xn[b].
// ---------------------------------------------------------------------------
__global__ __launch_bounds__(256) void selbits_kernel(
    const float* __restrict__ qattn, const float* __restrict__ xn,
    const float* __restrict__ outp_w, const float* __restrict__ outp_b,
    float* __restrict__ pairs) {
    int b  = blockIdx.x >> 4;
    int qg = blockIdx.x & 15;
    int d  = threadIdx.x;
    __shared__ float ws[8][64];
    float acc[8] = {};
    const float* xb = xn + (size_t)b * TT * DD;
    int g  = threadIdx.x >> 5;
    int tt = threadIdx.x & 31;
    const float* wbase = qattn + (size_t)(b * QQ + qg * 8 + g) * TT;

    for (int t0 = 0; t0 < TT; t0 += 64) {
        ws[g][tt]      = wbase[t0 + tt];
        ws[g][tt + 32] = wbase[t0 + tt + 32];
        __syncthreads();
        #pragma unroll 8
        for (int t = 0; t < 64; t++) {
            float x = xb[(size_t)(t0 + t) * DD + d];
            #pragma unroll
            for (int g2 = 0; g2 < 8; g2++) acc[g2] += ws[g2][t] * x;
        }
        __syncthreads();
    }

    float wd = outp_w[d];
    #pragma unroll
    for (int g2 = 0; g2 < 8; g2++) {
        float s = blockReduceSum256(acc[g2] * wd);
        if (d == 0)
            pairs[b * QQ + qg * 8 + g2] =
                1.f / (1.f + __expf(-(s + outp_b[0])));
    }
}

// ---------------------------------------------------------------------------
// 64-step recurrent MLP scan. One block per batch row, 64 threads.
// ---------------------------------------------------------------------------
__global__ __launch_bounds__(64) void scan_kernel(
    const float* __restrict__ pairs,
    const float* __restrict__ w1, const float* __restrict__ b1,
    const float* __restrict__ w2, const float* __restrict__ b2,
    const float* __restrict__ w3, const float* __restrict__ b3,
    float* __restrict__ sum_all) {
    int b = blockIdx.x;
    int j = threadIdx.x;
    __shared__ float h1[64], h2[64];
    __shared__ float carry;
    if (j == 0) carry = 0.f;

    float w1a = w1[j], w1b = w1[64 + j], w1c = w1[128 + j], bb1 = b1[j];
    float w2c[64];
    #pragma unroll
    for (int k = 0; k < 64; k++) w2c[k] = w2[k * 64 + j];
    float bb2 = b2[j];
    __syncthreads();

    for (int i = 0; i < 64; i++) {
        float z0 = pairs[b * QQ + i * 2];
        float z1 = pairs[b * QQ + i * 2 + 1];
        float z2 = carry;
        h1[j] = fmaxf(0.f, z0 * w1a + z1 * w1b + z2 * w1c + bb1);
        __syncthreads();
        float acc = bb2;
        #pragma unroll
        for (int k = 0; k < 64; k++) acc += h1[k] * w2c[k];
        h2[j] = fmaxf(0.f, acc);
        __syncthreads();
        if (j == 0) {
            float o0 = b3[0], o1 = b3[1];
            #pragma unroll
            for (int k = 0; k < 64; k++) {
                o0 += h2[k] * w3[k * 2];
                o1 += h2[k] * w3[k * 2 + 1];
            }
            o0 = 1.f / (1.f + __expf(-o0));
            o1 = 1.f / (1.f + __expf(-o1));
            sum_all[b * 65 + i] = o0;
            carry = o1;
        }
        __syncthreads();
    }
    if (j == 0) sum_all[b * 65 + 64] = carry;
}

// ---------------------------------------------------------------------------
// Launch
// ---------------------------------------------------------------------------
extern "C" void kernel_launch(void* const* d_in, const int* in_sizes, int n_in,
                              void* d_out, int out_size) {
    const int*   tokens   = (const int*)  d_in[0];
    const float* embed    = (const float*)d_in[1];
    const float* ln1_w    = (const float*)d_in[2];
    const float* ln1_b    = (const float*)d_in[3];
    const float* qkv_w    = (const float*)d_in[4];
    const float* qkv_b    = (const float*)d_in[5];
    const float* proj_w   = (const float*)d_in[6];
    const float* proj_b   = (const float*)d_in[7];
    const float* ln2_w    = (const float*)d_in[8];
    const float* ln2_b    = (const float*)d_in[9];
    const float* ffn1_w   = (const float*)d_in[10];
    const float* ffn1_b   = (const float*)d_in[11];
    const float* ffn2_w   = (const float*)d_in[12];
    const float* ffn2_b   = (const float*)d_in[13];
    const float* lnf_w    = (const float*)d_in[14];
    const float* lnf_b    = (const float*)d_in[15];
    const float* queries  = (const float*)d_in[16];
    const float* outp_w   = (const float*)d_in[17];
    const float* outp_b   = (const float*)d_in[18];
    const float* mlp_w1   = (const float*)d_in[19];
    const float* mlp_b1   = (const float*)d_in[20];
    const float* mlp_w2   = (const float*)d_in[21];
    const float* mlp_b2   = (const float*)d_in[22];
    const float* mlp_w3   = (const float*)d_in[23];
    const float* mlp_b3   = (const float*)d_in[24];

    float* out     = (float*)d_out;
    float* sum_all = out;                  // (B,65)   = 260
    float* pairs   = out + 260;            // (B,64,2) = 512
    float* qattn   = out + 772;            // (B,128,2048)

    float *px, *pxn, *pqkv;
    __nv_bfloat16 *pa1h, *pa1l, *pa2h, *pa2l, *pwh, *pwl;
    cudaGetSymbolAddress((void**)&px,   g_x);
    cudaGetSymbolAddress((void**)&pxn,  g_xn);
    cudaGetSymbolAddress((void**)&pqkv, g_qkv);
    cudaGetSymbolAddress((void**)&pa1h, g_a1h);
    cudaGetSymbolAddress((void**)&pa1l, g_a1l);
    cudaGetSymbolAddress((void**)&pa2h, g_a2h);
    cudaGetSymbolAddress((void**)&pa2l, g_a2l);
    cudaGetSymbolAddress((void**)&pwh,  g_wth);
    cudaGetSymbolAddress((void**)&pwl,  g_wtl);

    cudaFuncSetAttribute(fattn_kernel,
                         cudaFuncAttributeMaxDynamicSharedMemorySize, FATTN_SMEM);
    cudaFuncSetAttribute(gemm_bf16_kernel<0>,
                         cudaFuncAttributeMaxDynamicSharedMemorySize, GB_SMEM);
    cudaFuncSetAttribute(gemm_bf16_kernel<1>,
                         cudaFuncAttributeMaxDynamicSharedMemorySize, GB_SMEM);
    cudaFuncSetAttribute(gemm_bf16_kernel<2>,
                         cudaFuncAttributeMaxDynamicSharedMemorySize, GB_SMEM);

    const int ROWS = BB * TT;  // 8192

    embed_kernel<<<ROWS, 256>>>(tokens, embed, px);

    for (int l = 0; l < LL; l++) {
        // ---- attention block ----
        ln_split_kernel<<<ROWS, 256>>>(px, ln1_w + l * DD, ln1_b + l * DD,
                                       pa1h, pa1l);
        wsplitT_kernel<<<(3 * DD * DD) / 256, 256>>>(
            qkv_w + (size_t)l * DD * 3 * DD, pwh, pwl, DD, 3 * DD);
        gemm_bf16_kernel<0><<<dim3(6, ROWS / 128), 128, GB_SMEM>>>(
            pa1h, pa1l, pwh, pwl, qkv_b + l * 3 * DD, pqkv,
            (__nv_bfloat16*)nullptr, (__nv_bfloat16*)nullptr,
            ROWS, 3 * DD, DD);
        rope_kernel<<<ROWS, 256>>>(pqkv);
        fattn_kernel<<<dim3(TT / 64, HH, BB), 256, FATTN_SMEM>>>(pqkv, pa1h, pa1l);
        wsplitT_kernel<<<(DD * DD) / 256, 256>>>(
            proj_w + (size_t)l * DD * DD, pwh, pwl, DD, DD);
        gemm_bf16_kernel<2><<<dim3(2, ROWS / 128), 128, GB_SMEM>>>(
            pa1h, pa1l, pwh, pwl, proj_b + l * DD, px,
            (__nv_bfloat16*)nullptr, (__nv_bfloat16*)nullptr,
            ROWS, DD, DD);
        // ---- ffn block ----
        ln_split_kernel<<<ROWS, 256>>>(px, ln2_w + l * DD, ln2_b + l * DD,
                                       pa1h, pa1l);
        wsplitT_kernel<<<(4 * DD * DD) / 256, 256>>>(
            ffn1_w + (size_t)l * DD * 4 * DD, pwh, pwl, DD, 4 * DD);
        gemm_bf16_kernel<1><<<dim3(8, ROWS / 128), 128, GB_SMEM>>>(
            pa1h, pa1l, pwh, pwl, ffn1_b + l * 4 * DD, (float*)nullptr,
            pa2h, pa2l, ROWS, 4 * DD, DD);
        wsplitT_kernel<<<(4 * DD * DD) / 256, 256>>>(
            ffn2_w + (size_t)l * 4 * DD * DD, pwh, pwl, 4 * DD, DD);
        gemm_bf16_kernel<2><<<dim3(2, ROWS / 128), 128, GB_SMEM>>>(
            pa2h, pa2l, pwh, pwl, ffn2_b + l * DD, px,
            (__nv_bfloat16*)nullptr, (__nv_bfloat16*)nullptr,
            ROWS, DD, 4 * DD);
    }

    ln_kernel<<<ROWS, 256>>>(px, lnf_w, lnf_b, pxn);
    qscore_kernel<<<dim3(TT / 64, BB), 256>>>(pxn, queries, qattn);
    softmax2048_kernel<<<BB * QQ, 256>>>(qattn);
    selbits_kernel<<<BB * 16, 256>>>(qattn, pxn, outp_w, outp_b, pairs);
    scan_kernel<<<BB, 64>>>(pairs, mlp_w1, mlp_b1, mlp_w2, mlp_b2,
                            mlp_w3, mlp_b3, sum_all);
}

// round 13
// speedup vs baseline: 1.1829x; 1.1829x over previous
#include <cuda_runtime.h>
#include <cuda_bf16.h>
#include <math.h>
#include <stdint.h>

// ---------------------------------------------------------------------------
// Model dims (compile-time)
// ---------------------------------------------------------------------------
#define BB 4
#define TT 2048
#define DD 256
#define HH 4
#define HD 64
#define LL 2
#define QQ 128          // MAX_BITS*2 out queries

// ---------------------------------------------------------------------------
// Scratch (device globals; no runtime allocation allowed)
// ---------------------------------------------------------------------------
__device__ float g_x  [BB*TT*DD];        // residual stream
__device__ float g_xn [BB*TT*DD];        // final layernormed activations
__device__ float g_qkv[BB*TT*3*DD];      // qkv projections
__device__ __nv_bfloat16 g_a1h[BB*TT*DD],   g_a1l[BB*TT*DD];     // act split (D)
__device__ __nv_bfloat16 g_a2h[BB*TT*4*DD], g_a2l[BB*TT*4*DD];   // ffn hidden split
__device__ __nv_bfloat16 g_wth[4*DD*DD],    g_wtl[4*DD*DD];      // weight^T split

// ---------------------------------------------------------------------------
// bf16 split helpers + mma + cp.async
// ---------------------------------------------------------------------------
__device__ __forceinline__ void mma_bf16(float* c, const uint32_t* a,
                                         const uint32_t* b) {
    asm volatile(
        "mma.sync.aligned.m16n8k16.row.col.f32.bf16.bf16.f32 "
        "{%0,%1,%2,%3}, {%4,%5,%6,%7}, {%8,%9}, {%0,%1,%2,%3};"
        : "+f"(c[0]), "+f"(c[1]), "+f"(c[2]), "+f"(c[3])
        : "r"(a[0]), "r"(a[1]), "r"(a[2]), "r"(a[3]), "r"(b[0]), "r"(b[1]));
}

__device__ __forceinline__ uint32_t pack2bf(__nv_bfloat16 a, __nv_bfloat16 b) {
    return (uint32_t)__bfloat16_as_ushort(a) |
           ((uint32_t)__bfloat16_as_ushort(b) << 16);
}

__device__ __forceinline__ void split2(float x0, float x1,
                                       uint32_t& h, uint32_t& l) {
    __nv_bfloat16 h0 = __float2bfloat16(x0);
    __nv_bfloat16 h1 = __float2bfloat16(x1);
    __nv_bfloat16 l0 = __float2bfloat16(x0 - __bfloat162float(h0));
    __nv_bfloat16 l1 = __float2bfloat16(x1 - __bfloat162float(h1));
    h = pack2bf(h0, h1);
    l = pack2bf(l0, l1);
}

__device__ __forceinline__ uint32_t smem_u32(const void* p) {
    uint32_t a;
    asm("{ .reg .u64 t; cvta.to.shared.u64 t, %1; cvt.u32.u64 %0, t; }"
        : "=r"(a) : "l"(p));
    return a;
}

__device__ __forceinline__ void cpa16(uint32_t s, const void* g) {
    asm volatile("cp.async.cg.shared.global [%0], [%1], 16;"
                 :: "r"(s), "l"(g));
}
#define CPA_COMMIT() asm volatile("cp.async.commit_group;" ::: "memory")
#define CPA_WAIT0()  asm volatile("cp.async.wait_group 0;" ::: "memory")

// ---------------------------------------------------------------------------
// Reductions
// ---------------------------------------------------------------------------
__device__ __forceinline__ float blockReduceSum256(float v) {
    __shared__ float sh[8];
    int lane = threadIdx.x & 31, wid = threadIdx.x >> 5;
    #pragma unroll
    for (int o = 16; o; o >>= 1) v += __shfl_xor_sync(0xffffffffu, v, o);
    if (lane == 0) sh[wid] = v;
    __syncthreads();
    if (wid == 0) {
        float r = (lane < 8) ? sh[lane] : 0.f;
        #pragma unroll
        for (int o = 4; o; o >>= 1) r += __shfl_xor_sync(0xffffffffu, r, o);
        if (lane == 0) sh[0] = r;
    }
    __syncthreads();
    float r = sh[0];
    __syncthreads();
    return r;
}

__device__ __forceinline__ float blockReduceMax256(float v) {
    __shared__ float sh[8];
    int lane = threadIdx.x & 31, wid = threadIdx.x >> 5;
    #pragma unroll
    for (int o = 16; o; o >>= 1) v = fmaxf(v, __shfl_xor_sync(0xffffffffu, v, o));
    if (lane == 0) sh[wid] = v;
    __syncthreads();
    if (wid == 0) {
        float r = (lane < 8) ? sh[lane] : -1e30f;
        #pragma unroll
        for (int o = 4; o; o >>= 1) r = fmaxf(r, __shfl_xor_sync(0xffffffffu, r, o));
        if (lane == 0) sh[0] = r;
    }
    __syncthreads();
    float r = sh[0];
    __syncthreads();
    return r;
}

// ---------------------------------------------------------------------------
// Embedding lookup
// ---------------------------------------------------------------------------
__global__ void embed_kernel(const int* __restrict__ tokens,
                             const float* __restrict__ embed,
                             float* __restrict__ x) {
    int row = blockIdx.x;
    int d   = threadIdx.x;
    int tok = tokens[row];
    x[(size_t)row * DD + d] = embed[(size_t)tok * DD + d];
}

// ---------------------------------------------------------------------------
// LayerNorm over D=256 -> fp32
// ---------------------------------------------------------------------------
__global__ void ln_kernel(const float* __restrict__ x,
                          const float* __restrict__ w,
                          const float* __restrict__ b,
                          float* __restrict__ y) {
    int row = blockIdx.x;
    int d   = threadIdx.x;
    float v  = x[(size_t)row * DD + d];
    float mu = blockReduceSum256(v) * (1.f / DD);
    float dv = v - mu;
    float var = blockReduceSum256(dv * dv) * (1.f / DD);
    float r = rsqrtf(var + 1e-5f);
    y[(size_t)row * DD + d] = dv * r * w[d] + b[d];
}

// ---------------------------------------------------------------------------
// LayerNorm -> bf16 hi/lo split
// ---------------------------------------------------------------------------
__global__ void ln_split_kernel(const float* __restrict__ x,
                                const float* __restrict__ w,
                                const float* __restrict__ b,
                                __nv_bfloat16* __restrict__ oh,
                                __nv_bfloat16* __restrict__ ol) {
    int row = blockIdx.x;
    int d   = threadIdx.x;
    float v  = x[(size_t)row * DD + d];
    float mu = blockReduceSum256(v) * (1.f / DD);
    float dv = v - mu;
    float var = blockReduceSum256(dv * dv) * (1.f / DD);
    float r = rsqrtf(var + 1e-5f);
    float y = dv * r * w[d] + b[d];
    __nv_bfloat16 h = __float2bfloat16(y);
    size_t i = (size_t)row * DD + d;
    oh[i] = h;
    ol[i] = __float2bfloat16(y - __bfloat162float(h));
}

// ---------------------------------------------------------------------------
// Weight split + transpose: W[K][N] fp32 -> T[N][K] bf16 hi/lo
// ---------------------------------------------------------------------------
__global__ void wsplitT_kernel(const float* __restrict__ W,
                               __nv_bfloat16* __restrict__ Th,
                               __nv_bfloat16* __restrict__ Tl,
                               int K, int N) {
    int idx = blockIdx.x * 256 + threadIdx.x;   // n*K + k
    int n = idx / K, k = idx - n * K;
    float v = W[(size_t)k * N + n];
    __nv_bfloat16 h = __float2bfloat16(v);
    Th[idx] = h;
    Tl[idx] = __float2bfloat16(v - __bfloat162float(h));
}

// ---------------------------------------------------------------------------
// Pre-split bf16 HMMA GEMM, cp.async 2-stage (R11-validated shape).
// CTA 128x128, 8 warps (2x4), warp 64x32, BK=32, smem stride 40.
// ---------------------------------------------------------------------------
#define TST 40
#define STAGE_ELEMS (4 * 128 * TST)
#define GB_SMEM (2 * STAGE_ELEMS * 2)

template <int EPI>
__global__ __launch_bounds__(256, 2) void gemm_bf16_kernel(
    const __nv_bfloat16* __restrict__ Ahg, const __nv_bfloat16* __restrict__ Alg,
    const __nv_bfloat16* __restrict__ Bhg, const __nv_bfloat16* __restrict__ Blg,
    const float* __restrict__ bias, float* __restrict__ C,
    __nv_bfloat16* __restrict__ Chi, __nv_bfloat16* __restrict__ Clo,
    int M, int N, int K) {
    extern __shared__ __nv_bfloat16 smb[];
    const uint32_t sbase = smem_u32(smb);

    const int tid  = threadIdx.x;
    const int warp = tid >> 5, lane = tid & 31;
    const int g = lane >> 2, tig = lane & 3;
    const int wm = (warp & 1) * 64, wn = (warp >> 1) * 32;
    const int bm = blockIdx.y * 128, bn = blockIdx.x * 128;

    float acc[4][4][4];
    #pragma unroll
    for (int mf = 0; mf < 4; mf++)
        #pragma unroll
        for (int nf = 0; nf < 4; nf++)
            #pragma unroll
            for (int c = 0; c < 4; c++) acc[mf][nf][c] = 0.f;

    const int ar = tid >> 1, aks = (tid & 1) * 16;
    const uint32_t soA = ar * TST + aks;

    auto issue = [&](int st, int k0) {
        uint32_t sb = sbase + (uint32_t)(st * STAGE_ELEMS) * 2;
        const __nv_bfloat16* ga_h = Ahg + (size_t)(bm + ar) * K + k0 + aks;
        const __nv_bfloat16* ga_l = Alg + (size_t)(bm + ar) * K + k0 + aks;
        const __nv_bfloat16* gb_h = Bhg + (size_t)(bn + ar) * K + k0 + aks;
        const __nv_bfloat16* gb_l = Blg + (size_t)(bn + ar) * K + k0 + aks;
        cpa16(sb + (soA) * 2,                        ga_h);
        cpa16(sb + (soA + 8) * 2,                    ga_h + 8);
        cpa16(sb + (128 * TST + soA) * 2,            ga_l);
        cpa16(sb + (128 * TST + soA + 8) * 2,        ga_l + 8);
        cpa16(sb + (2 * 128 * TST + soA) * 2,        gb_h);
        cpa16(sb + (2 * 128 * TST + soA + 8) * 2,    gb_h + 8);
        cpa16(sb + (3 * 128 * TST + soA) * 2,        gb_l);
        cpa16(sb + (3 * 128 * TST + soA + 8) * 2,    gb_l + 8);
        CPA_COMMIT();
    };

    const int NT = K >> 5;
    issue(0, 0);

    for (int kt = 0; kt < NT; kt++) {
        CPA_WAIT0();
        __syncthreads();
        if (kt + 1 < NT) issue((kt + 1) & 1, (kt + 1) * 32);

        const __nv_bfloat16* Ah = smb + (kt & 1) * STAGE_ELEMS;
        const __nv_bfloat16* Al = Ah + 128 * TST;
        const __nv_bfloat16* Bh = Al + 128 * TST;
        const __nv_bfloat16* Bl = Bh + 128 * TST;

        #pragma unroll
        for (int ks2 = 0; ks2 < 2; ks2++) {
            const int kb = ks2 * 16;
            uint32_t bhf[4][2], blf[4][2];
            #pragma unroll
            for (int nf = 0; nf < 4; nf++) {
                int n0 = wn + nf * 8 + g;
                uint32_t o0 = n0 * TST + kb + tig * 2;
                bhf[nf][0] = *(const uint32_t*)&Bh[o0];
                bhf[nf][1] = *(const uint32_t*)&Bh[o0 + 8];
                blf[nf][0] = *(const uint32_t*)&Bl[o0];
                blf[nf][1] = *(const uint32_t*)&Bl[o0 + 8];
            }
            #pragma unroll
            for (int mf = 0; mf < 4; mf++) {
                int r0 = wm + mf * 16 + g;
                uint32_t oa = r0 * TST + kb + tig * 2;
                uint32_t ob = (r0 + 8) * TST + kb + tig * 2;
                uint32_t ahf[4], alf[4];
                ahf[0] = *(const uint32_t*)&Ah[oa];
                ahf[1] = *(const uint32_t*)&Ah[ob];
                ahf[2] = *(const uint32_t*)&Ah[oa + 8];
                ahf[3] = *(const uint32_t*)&Ah[ob + 8];
                alf[0] = *(const uint32_t*)&Al[oa];
                alf[1] = *(const uint32_t*)&Al[ob];
                alf[2] = *(const uint32_t*)&Al[oa + 8];
                alf[3] = *(const uint32_t*)&Al[ob + 8];
                #pragma unroll
                for (int nf = 0; nf < 4; nf++) {
                    mma_bf16(acc[mf][nf], ahf, bhf[nf]);
                    mma_bf16(acc[mf][nf], ahf, blf[nf]);
                    mma_bf16(acc[mf][nf], alf, bhf[nf]);
                }
            }
        }
    }

    #pragma unroll
    for (int mf = 0; mf < 4; mf++) {
        #pragma unroll
        for (int nf = 0; nf < 4; nf++) {
            float* cc = acc[mf][nf];
            int r0 = bm + wm + mf * 16 + g;
            int c0 = bn + wn + nf * 8 + tig * 2;
            float bv0 = bias[c0], bv1 = bias[c0 + 1];
            float v0 = cc[0] + bv0, v1 = cc[1] + bv1;
            float v2 = cc[2] + bv0, v3 = cc[3] + bv1;
            if (EPI == 1) {
                v0 = 0.5f * v0 * (1.f + erff(v0 * 0.70710678118654752f));
                v1 = 0.5f * v1 * (1.f + erff(v1 * 0.70710678118654752f));
                v2 = 0.5f * v2 * (1.f + erff(v2 * 0.70710678118654752f));
                v3 = 0.5f * v3 * (1.f + erff(v3 * 0.70710678118654752f));
                uint32_t h, l;
                split2(v0, v1, h, l);
                *(uint32_t*)(Chi + (size_t)r0 * N + c0) = h;
                *(uint32_t*)(Clo + (size_t)r0 * N + c0) = l;
                split2(v2, v3, h, l);
                *(uint32_t*)(Chi + (size_t)(r0 + 8) * N + c0) = h;
                *(uint32_t*)(Clo + (size_t)(r0 + 8) * N + c0) = l;
            } else {
                if (EPI == 2) {
                    float2 o0 = *(const float2*)(C + (size_t)r0 * N + c0);
                    float2 o1 = *(const float2*)(C + (size_t)(r0 + 8) * N + c0);
                    v0 += o0.x; v1 += o0.y; v2 += o1.x; v3 += o1.y;
                }
                float2 s0; s0.x = v0; s0.y = v1;
                float2 s1; s1.x = v2; s1.y = v3;
                *(float2*)(C + (size_t)r0 * N + c0)       = s0;
                *(float2*)(C + (size_t)(r0 + 8) * N + c0) = s1;
            }
        }
    }
}

// ---------------------------------------------------------------------------
// RoPE applied in-place to q and k parts of g_qkv.
// ---------------------------------------------------------------------------
__global__ void rope_kernel(float* __restrict__ qkv) {
    int idx  = blockIdx.x * blockDim.x + threadIdx.x;
    int d    = idx & 31;
    int h    = (idx >> 5) & 3;
    int part = (idx >> 7) & 1;
    int row  = idx >> 8;           // b*T + t
    int t    = row & (TT - 1);
    float inv = powf(10000.f, -(float)d * (1.f / 32.f));
    float ang = (float)t * inv;
    float s, c;
    sincosf(ang, &s, &c);
    float* p = qkv + (size_t)row * (3 * DD) + part * DD + h * HD;
    float x0 = p[d], x1 = p[d + 32];
    p[d]      = x0 * c - x1 * s;
    p[d + 32] = x1 * c + x0 * s;
}

// ---------------------------------------------------------------------------
// Hybrid flash attention: HMMA QK^T (plain bf16) + frag softmax + fp32 PV.
// One block per (b, h, 64-q tile), 128 threads = 4 warps.
// Warp w owns query rows 16w..16w+15 for scores/softmax (R9-validated maps);
// PV phase re-grids threads as (tyi=tid>>4 in 0..7) x (txd=tid&15).
// Epilogue writes bf16 hi/lo (feeds proj GEMM).
// ---------------------------------------------------------------------------
#define FST 72
#define PS_STRIDE 68
#define FATTN_SMEM (2*64*FST*2 + 64*64*4 + 64*PS_STRIDE*4 + 2*64*4)

__global__ __launch_bounds__(128) void fattn_kernel(
    const float* __restrict__ qkv,
    __nv_bfloat16* __restrict__ oh, __nv_bfloat16* __restrict__ ol) {
    extern __shared__ char fsm[];
    __nv_bfloat16* Qb = (__nv_bfloat16*)fsm;           // [64][FST]
    __nv_bfloat16* Kb = Qb + 64 * FST;                 // [64][FST]
    float* Vs     = (float*)(fsm + 2 * 64 * FST * 2);  // [64][64]
    float* Ps     = Vs + 64 * 64;                      // [s][i], stride 68
    float* corr_s = Ps + 64 * PS_STRIDE;               // [64]
    float* linv_s = corr_s + 64;                       // [64]

    const int qt = (gridDim.x - 1) - blockIdx.x;
    const int h  = blockIdx.y;
    const int b  = blockIdx.z;
    const int tid = threadIdx.x;
    const int warp = tid >> 5, lane = tid & 31;
    const int g = lane >> 2, tig = lane & 3;
    const int wm16 = warp * 16;
    const int r0 = wm16 + g, r1 = r0 + 8;

    const int lr = tid >> 1;          // 0..63
    const int lc = (tid & 1) * 32;    // 0 or 32

    const int txd = tid & 15, tyi = tid >> 4;   // PV grid

    const float* base = qkv + (size_t)b * TT * (3 * DD);

    // ---- stage Q (scaled, plain bf16) ----
    {
        const float* qrow = base + (size_t)(qt * 64 + lr) * (3 * DD) + h * HD + lc;
        #pragma unroll
        for (int m = 0; m < 8; m++) {
            float4 v = *(const float4*)(qrow + m * 4);
            uint32_t p0 = pack2bf(__float2bfloat16(v.x * 0.125f),
                                  __float2bfloat16(v.y * 0.125f));
            uint32_t p1 = pack2bf(__float2bfloat16(v.z * 0.125f),
                                  __float2bfloat16(v.w * 0.125f));
            uint32_t off = lr * FST + lc + m * 4;
            *(uint32_t*)&Qb[off]     = p0;
            *(uint32_t*)&Qb[off + 2] = p1;
        }
    }

    float m0 = -1e30f, m1 = -1e30f, l0s = 0.f, l1s = 0.f;
    float acc[8][4];
    #pragma unroll
    for (int ii = 0; ii < 8; ii++)
        #pragma unroll
        for (int j = 0; j < 4; j++) acc[ii][j] = 0.f;

    for (int kt = 0; kt <= qt; kt++) {
        __syncthreads();   // prev PV done reading Ps/Vs; Q staged (first iter)
        // ---- stage K (plain bf16) + V (fp32 natural) ----
        {
            const float* krow = base + (size_t)(kt * 64 + lr) * (3 * DD) + DD + h * HD + lc;
            #pragma unroll
            for (int m = 0; m < 8; m++) {
                float4 v = *(const float4*)(krow + m * 4);
                uint32_t p0 = pack2bf(__float2bfloat16(v.x), __float2bfloat16(v.y));
                uint32_t p1 = pack2bf(__float2bfloat16(v.z), __float2bfloat16(v.w));
                uint32_t off = lr * FST + lc + m * 4;
                *(uint32_t*)&Kb[off]     = p0;
                *(uint32_t*)&Kb[off + 2] = p1;
            }
            const float* vrow = base + (size_t)(kt * 64 + lr) * (3 * DD) + 2 * DD + h * HD + lc;
            #pragma unroll
            for (int m = 0; m < 8; m++)
                *(float4*)&Vs[lr * 64 + lc + m * 4] = *(const float4*)(vrow + m * 4);
        }
        __syncthreads();

        // ---- S = Q K^T via HMMA (warp rows wm16..+15, 64 s-cols) ----
        float sf[8][4];
        #pragma unroll
        for (int j = 0; j < 8; j++)
            #pragma unroll
            for (int c = 0; c < 4; c++) sf[j][c] = 0.f;

        #pragma unroll
        for (int ks = 0; ks < 4; ks++) {
            uint32_t oa = r0 * FST + ks * 16 + tig * 2;
            uint32_t ob = r1 * FST + ks * 16 + tig * 2;
            uint32_t qa[4];
            qa[0] = *(const uint32_t*)&Qb[oa];
            qa[1] = *(const uint32_t*)&Qb[ob];
            qa[2] = *(const uint32_t*)&Qb[oa + 8];
            qa[3] = *(const uint32_t*)&Qb[ob + 8];
            #pragma unroll
            for (int j = 0; j < 8; j++) {
                int n0 = j * 8 + g;
                uint32_t okb = n0 * FST + ks * 16 + tig * 2;
                uint32_t bh[2];
                bh[0] = *(const uint32_t*)&Kb[okb];
                bh[1] = *(const uint32_t*)&Kb[okb + 8];
                mma_bf16(sf[j], qa, bh);
            }
        }

        // ---- causal mask on diagonal tile ----
        if (kt == qt) {
            #pragma unroll
            for (int j = 0; j < 8; j++) {
                int c0 = j * 8 + tig * 2;
                if (c0     > r0) sf[j][0] = -1e30f;
                if (c0 + 1 > r0) sf[j][1] = -1e30f;
                if (c0     > r1) sf[j][2] = -1e30f;
                if (c0 + 1 > r1) sf[j][3] = -1e30f;
            }
        }

        // ---- online softmax in frag layout (quad reduce over tig) ----
        float rm0 = -1e30f, rm1 = -1e30f;
        #pragma unroll
        for (int j = 0; j < 8; j++) {
            rm0 = fmaxf(rm0, fmaxf(sf[j][0], sf[j][1]));
            rm1 = fmaxf(rm1, fmaxf(sf[j][2], sf[j][3]));
        }
        rm0 = fmaxf(rm0, __shfl_xor_sync(0xffffffffu, rm0, 1));
        rm0 = fmaxf(rm0, __shfl_xor_sync(0xffffffffu, rm0, 2));
        rm1 = fmaxf(rm1, __shfl_xor_sync(0xffffffffu, rm1, 1));
        rm1 = fmaxf(rm1, __shfl_xor_sync(0xffffffffu, rm1, 2));
        float nm0 = fmaxf(m0, rm0), nm1 = fmaxf(m1, rm1);
        float cr0 = __expf(m0 - nm0), cr1 = __expf(m1 - nm1);
        m0 = nm0; m1 = nm1;
        float rs0 = 0.f, rs1 = 0.f;
        #pragma unroll
        for (int j = 0; j < 8; j++) {
            sf[j][0] = __expf(sf[j][0] - nm0);
            sf[j][1] = __expf(sf[j][1] - nm0);
            sf[j][2] = __expf(sf[j][2] - nm1);
            sf[j][3] = __expf(sf[j][3] - nm1);
            rs0 += sf[j][0] + sf[j][1];
            rs1 += sf[j][2] + sf[j][3];
        }
        rs0 += __shfl_xor_sync(0xffffffffu, rs0, 1);
        rs0 += __shfl_xor_sync(0xffffffffu, rs0, 2);
        rs1 += __shfl_xor_sync(0xffffffffu, rs1, 1);
        rs1 += __shfl_xor_sync(0xffffffffu, rs1, 2);
        l0s = l0s * cr0 + rs0;
        l1s = l1s * cr1 + rs1;

        // ---- write P to Ps[s][i] + per-row corr ----
        #pragma unroll
        for (int j = 0; j < 8; j++) {
            int c = j * 8 + tig * 2;
            Ps[c * PS_STRIDE + r0]       = sf[j][0];
            Ps[(c + 1) * PS_STRIDE + r0] = sf[j][1];
            Ps[c * PS_STRIDE + r1]       = sf[j][2];
            Ps[(c + 1) * PS_STRIDE + r1] = sf[j][3];
        }
        if (tig == 0) { corr_s[r0] = cr0; corr_s[r1] = cr1; }
        __syncthreads();

        // ---- fp32 PV: rows tyi*8..+7, cols txd*4..+3 ----
        {
            float cl[8];
            #pragma unroll
            for (int ii = 0; ii < 8; ii++) cl[ii] = corr_s[tyi * 8 + ii];
            #pragma unroll
            for (int ii = 0; ii < 8; ii++)
                #pragma unroll
                for (int j = 0; j < 4; j++) acc[ii][j] *= cl[ii];

            #pragma unroll 4
            for (int ss = 0; ss < 64; ss++) {
                float4 pa0 = *(const float4*)&Ps[ss * PS_STRIDE + tyi * 8];
                float4 pa1 = *(const float4*)&Ps[ss * PS_STRIDE + tyi * 8 + 4];
                float4 vb  = *(const float4*)&Vs[ss * 64 + txd * 4];
                float pr[8] = {pa0.x, pa0.y, pa0.z, pa0.w,
                               pa1.x, pa1.y, pa1.z, pa1.w};
                float vr[4] = {vb.x, vb.y, vb.z, vb.w};
                #pragma unroll
                for (int ii = 0; ii < 8; ii++)
                    #pragma unroll
                    for (int j = 0; j < 4; j++)
                        acc[ii][j] += pr[ii] * vr[j];
            }
        }
    }

    // ---- epilogue: normalize + bf16 hi/lo split ----
    if (tig == 0) { linv_s[r0] = 1.f / l0s; linv_s[r1] = 1.f / l1s; }
    __syncthreads();
    #pragma unroll
    for (int ii = 0; ii < 8; ii++) {
        float li = linv_s[tyi * 8 + ii];
        int t = qt * 64 + tyi * 8 + ii;
        float v0 = acc[ii][0] * li, v1 = acc[ii][1] * li;
        float v2 = acc[ii][2] * li, v3 = acc[ii][3] * li;
        uint32_t h0, l0, h1, l1;
        split2(v0, v1, h0, l0);
        split2(v2, v3, h1, l1);
        size_t idx = (size_t)(b * TT + t) * DD + h * HD + txd * 4;
        *(uint32_t*)(oh + idx)     = h0;
        *(uint32_t*)(oh + idx + 2) = h1;
        *(uint32_t*)(ol + idx)     = l0;
        *(uint32_t*)(ol + idx + 2) = l1;
    }
}

// ---------------------------------------------------------------------------
// q_scores as GEMM: C[q,t] = (1/16) * queries[q,:].xn[b,t,:]
// ---------------------------------------------------------------------------
__global__ __launch_bounds__(256) void qscore_kernel(
    const float* __restrict__ xn, const float* __restrict__ queries,
    float* __restrict__ qattn) {
    __shared__ float Qs[2][8][128];
    __shared__ float Xs[2][8][64];
    int b  = blockIdx.y;
    int t0 = blockIdx.x * 64;
    int tid = threadIdx.x;
    int tx = tid & 15, ty = tid >> 4;

    int qr = tid >> 1, qc = (tid & 1) * 4;
    int xr = tid >> 1, xc = (tid & 1) * 4;
    bool xact = tid < 128;
    const float* xb = xn + (size_t)b * TT * DD;

    float acc[8][4];
    #pragma unroll
    for (int i = 0; i < 8; i++)
        #pragma unroll
        for (int j = 0; j < 4; j++) acc[i][j] = 0.f;

    {
        float4 qv = *(const float4*)(queries + qr * DD + qc);
        Qs[0][qc + 0][qr] = qv.x; Qs[0][qc + 1][qr] = qv.y;
        Qs[0][qc + 2][qr] = qv.z; Qs[0][qc + 3][qr] = qv.w;
        if (xact) {
            float4 xv = *(const float4*)(xb + (size_t)(t0 + xr) * DD + xc);
            Xs[0][xc + 0][xr] = xv.x; Xs[0][xc + 1][xr] = xv.y;
            Xs[0][xc + 2][xr] = xv.z; Xs[0][xc + 3][xr] = xv.w;
        }
    }
    __syncthreads();

    const int NT = DD >> 3;   // 32
    for (int kt = 0; kt < NT; kt++) {
        int cur = kt & 1;
        float4 qv, xv;
        if (kt + 1 < NT) {
            qv = *(const float4*)(queries + qr * DD + (kt + 1) * 8 + qc);
            if (xact)
                xv = *(const float4*)(xb + (size_t)(t0 + xr) * DD + (kt + 1) * 8 + xc);
        }
        #pragma unroll
        for (int kk = 0; kk < 8; kk++) {
            float a0[8], b0[4];
            *(float4*)&a0[0] = *(const float4*)&Qs[cur][kk][ty * 4];
            *(float4*)&a0[4] = *(const float4*)&Qs[cur][kk][64 + ty * 4];
            *(float4*)&b0[0] = *(const float4*)&Xs[cur][kk][tx * 4];
            #pragma unroll
            for (int i = 0; i < 8; i++)
                #pragma unroll
                for (int j = 0; j < 4; j++)
                    acc[i][j] += a0[i] * b0[j];
        }
        if (kt + 1 < NT) {
            int nxt = cur ^ 1;
            Qs[nxt][qc + 0][qr] = qv.x; Qs[nxt][qc + 1][qr] = qv.y;
            Qs[nxt][qc + 2][qr] = qv.z; Qs[nxt][qc + 3][qr] = qv.w;
            if (xact) {
                Xs[nxt][xc + 0][xr] = xv.x; Xs[nxt][xc + 1][xr] = xv.y;
                Xs[nxt][xc + 2][xr] = xv.z; Xs[nxt][xc + 3][xr] = xv.w;
            }
            __syncthreads();
        }
    }

    #pragma unroll
    for (int i = 0; i < 8; i++) {
        int q = (i < 4) ? ty * 4 + i : 64 + ty * 4 + (i - 4);
        float4 o;
        o.x = acc[i][0] * 0.0625f; o.y = acc[i][1] * 0.0625f;
        o.z = acc[i][2] * 0.0625f; o.w = acc[i][3] * 0.0625f;
        *(float4*)(qattn + (size_t)(b * QQ + q) * TT + t0 + tx * 4) = o;
    }
}

// ---------------------------------------------------------------------------
// Softmax over last dim (2048), in place. One block per row.
// ---------------------------------------------------------------------------
__global__ __launch_bounds__(256) void softmax2048_kernel(float* __restrict__ p) {
    float* row = p + (size_t)blockIdx.x * TT;
    int tid = threadIdx.x;
    float v[8];
    float mx = -1e30f;
    #pragma unroll
    for (int j = 0; j < 8; j++) { v[j] = row[tid + 256 * j]; mx = fmaxf(mx, v[j]); }
    mx = blockReduceMax256(mx);
    float s = 0.f;
    #pragma unroll
    for (int j = 0; j < 8; j++) { v[j] = __expf(v[j] - mx); s += v[j]; }
    s = blockReduceSum256(s);
    float inv = 1.f / s;
    #pragma unroll
    for (int j = 0; j < 8; j++) row[tid + 256 * j] = v[j] * inv;
}

// ---------------------------------------------------------------------------
// selbits: 8 query rows per block share one streaming pass over xn[b].
// ---------------------------------------------------------------------------
__global__ __launch_bounds__(256) void selbits_kernel(
    const float* __restrict__ qattn, const float* __restrict__ xn,
    const float* __restrict__ outp_w, const float* __restrict__ outp_b,
    float* __restrict__ pairs) {
    int b  = blockIdx.x >> 4;
    int qg = blockIdx.x & 15;
    int d  = threadIdx.x;
    __shared__ float ws[8][64];
    float acc[8] = {};
    const float* xb = xn + (size_t)b * TT * DD;
    int g  = threadIdx.x >> 5;
    int tt = threadIdx.x & 31;
    const float* wbase = qattn + (size_t)(b * QQ + qg * 8 + g) * TT;

    for (int t0 = 0; t0 < TT; t0 += 64) {
        ws[g][tt]      = wbase[t0 + tt];
        ws[g][tt + 32] = wbase[t0 + tt + 32];
        __syncthreads();
        #pragma unroll 8
        for (int t = 0; t < 64; t++) {
            float x = xb[(size_t)(t0 + t) * DD + d];
            #pragma unroll
            for (int g2 = 0; g2 < 8; g2++) acc[g2] += ws[g2][t] * x;
        }
        __syncthreads();
    }

    float wd = outp_w[d];
    #pragma unroll
    for (int g2 = 0; g2 < 8; g2++) {
        float s = blockReduceSum256(acc[g2] * wd);
        if (d == 0)
            pairs[b * QQ + qg * 8 + g2] =
                1.f / (1.f + __expf(-(s + outp_b[0])));
    }
}

// ---------------------------------------------------------------------------
// 64-step recurrent MLP scan. One block per batch row, 64 threads.
// ---------------------------------------------------------------------------
__global__ __launch_bounds__(64) void scan_kernel(
    const float* __restrict__ pairs,
    const float* __restrict__ w1, const float* __restrict__ b1,
    const float* __restrict__ w2, const float* __restrict__ b2,
    const float* __restrict__ w3, const float* __restrict__ b3,
    float* __restrict__ sum_all) {
    int b = blockIdx.x;
    int j = threadIdx.x;
    __shared__ float h1[64], h2[64];
    __shared__ float carry;
    if (j == 0) carry = 0.f;

    float w1a = w1[j], w1b = w1[64 + j], w1c = w1[128 + j], bb1 = b1[j];
    float w2c[64];
    #pragma unroll
    for (int k = 0; k < 64; k++) w2c[k] = w2[k * 64 + j];
    float bb2 = b2[j];
    __syncthreads();

    for (int i = 0; i < 64; i++) {
        float z0 = pairs[b * QQ + i * 2];
        float z1 = pairs[b * QQ + i * 2 + 1];
        float z2 = carry;
        h1[j] = fmaxf(0.f, z0 * w1a + z1 * w1b + z2 * w1c + bb1);
        __syncthreads();
        float acc = bb2;
        #pragma unroll
        for (int k = 0; k < 64; k++) acc += h1[k] * w2c[k];
        h2[j] = fmaxf(0.f, acc);
        __syncthreads();
        if (j == 0) {
            float o0 = b3[0], o1 = b3[1];
            #pragma unroll
            for (int k = 0; k < 64; k++) {
                o0 += h2[k] * w3[k * 2];
                o1 += h2[k] * w3[k * 2 + 1];
            }
            o0 = 1.f / (1.f + __expf(-o0));
            o1 = 1.f / (1.f + __expf(-o1));
            sum_all[b * 65 + i] = o0;
            carry = o1;
        }
        __syncthreads();
    }
    if (j == 0) sum_all[b * 65 + 64] = carry;
}

// ---------------------------------------------------------------------------
// Launch
// ---------------------------------------------------------------------------
extern "C" void kernel_launch(void* const* d_in, const int* in_sizes, int n_in,
                              void* d_out, int out_size) {
    const int*   tokens   = (const int*)  d_in[0];
    const float* embed    = (const float*)d_in[1];
    const float* ln1_w    = (const float*)d_in[2];
    const float* ln1_b    = (const float*)d_in[3];
    const float* qkv_w    = (const float*)d_in[4];
    const float* qkv_b    = (const float*)d_in[5];
    const float* proj_w   = (const float*)d_in[6];
    const float* proj_b   = (const float*)d_in[7];
    const float* ln2_w    = (const float*)d_in[8];
    const float* ln2_b    = (const float*)d_in[9];
    const float* ffn1_w   = (const float*)d_in[10];
    const float* ffn1_b   = (const float*)d_in[11];
    const float* ffn2_w   = (const float*)d_in[12];
    const float* ffn2_b   = (const float*)d_in[13];
    const float* lnf_w    = (const float*)d_in[14];
    const float* lnf_b    = (const float*)d_in[15];
    const float* queries  = (const float*)d_in[16];
    const float* outp_w   = (const float*)d_in[17];
    const float* outp_b   = (const float*)d_in[18];
    const float* mlp_w1   = (const float*)d_in[19];
    const float* mlp_b1   = (const float*)d_in[20];
    const float* mlp_w2   = (const float*)d_in[21];
    const float* mlp_b2   = (const float*)d_in[22];
    const float* mlp_w3   = (const float*)d_in[23];
    const float* mlp_b3   = (const float*)d_in[24];

    float* out     = (float*)d_out;
    float* sum_all = out;                  // (B,65)   = 260
    float* pairs   = out + 260;            // (B,64,2) = 512
    float* qattn   = out + 772;            // (B,128,2048)

    float *px, *pxn, *pqkv;
    __nv_bfloat16 *pa1h, *pa1l, *pa2h, *pa2l, *pwh, *pwl;
    cudaGetSymbolAddress((void**)&px,   g_x);
    cudaGetSymbolAddress((void**)&pxn,  g_xn);
    cudaGetSymbolAddress((void**)&pqkv, g_qkv);
    cudaGetSymbolAddress((void**)&pa1h, g_a1h);
    cudaGetSymbolAddress((void**)&pa1l, g_a1l);
    cudaGetSymbolAddress((void**)&pa2h, g_a2h);
    cudaGetSymbolAddress((void**)&pa2l, g_a2l);
    cudaGetSymbolAddress((void**)&pwh,  g_wth);
    cudaGetSymbolAddress((void**)&pwl,  g_wtl);

    cudaFuncSetAttribute(fattn_kernel,
                         cudaFuncAttributeMaxDynamicSharedMemorySize, FATTN_SMEM);
    cudaFuncSetAttribute(gemm_bf16_kernel<0>,
                         cudaFuncAttributeMaxDynamicSharedMemorySize, GB_SMEM);
    cudaFuncSetAttribute(gemm_bf16_kernel<1>,
                         cudaFuncAttributeMaxDynamicSharedMemorySize, GB_SMEM);
    cudaFuncSetAttribute(gemm_bf16_kernel<2>,
                         cudaFuncAttributeMaxDynamicSharedMemorySize, GB_SMEM);

    const int ROWS = BB * TT;  // 8192

    embed_kernel<<<ROWS, 256>>>(tokens, embed, px);

    for (int l = 0; l < LL; l++) {
        // ---- attention block ----
        ln_split_kernel<<<ROWS, 256>>>(px, ln1_w + l * DD, ln1_b + l * DD,
                                       pa1h, pa1l);
        wsplitT_kernel<<<(3 * DD * DD) / 256, 256>>>(
            qkv_w + (size_t)l * DD * 3 * DD, pwh, pwl, DD, 3 * DD);
        gemm_bf16_kernel<0><<<dim3(6, ROWS / 128), 256, GB_SMEM>>>(
            pa1h, pa1l, pwh, pwl, qkv_b + l * 3 * DD, pqkv,
            (__nv_bfloat16*)nullptr, (__nv_bfloat16*)nullptr,
            ROWS, 3 * DD, DD);
        rope_kernel<<<ROWS, 256>>>(pqkv);
        fattn_kernel<<<dim3(TT / 64, HH, BB), 128, FATTN_SMEM>>>(pqkv, pa1h, pa1l);
        wsplitT_kernel<<<(DD * DD) / 256, 256>>>(
            proj_w + (size_t)l * DD * DD, pwh, pwl, DD, DD);
        gemm_bf16_kernel<2><<<dim3(2, ROWS / 128), 256, GB_SMEM>>>(
            pa1h, pa1l, pwh, pwl, proj_b + l * DD, px,
            (__nv_bfloat16*)nullptr, (__nv_bfloat16*)nullptr,
            ROWS, DD, DD);
        // ---- ffn block ----
        ln_split_kernel<<<ROWS, 256>>>(px, ln2_w + l * DD, ln2_b + l * DD,
                                       pa1h, pa1l);
        wsplitT_kernel<<<(4 * DD * DD) / 256, 256>>>(
            ffn1_w + (size_t)l * DD * 4 * DD, pwh, pwl, DD, 4 * DD);
        gemm_bf16_kernel<1><<<dim3(8, ROWS / 128), 256, GB_SMEM>>>(
            pa1h, pa1l, pwh, pwl, ffn1_b + l * 4 * DD, (float*)nullptr,
            pa2h, pa2l, ROWS, 4 * DD, DD);
        wsplitT_kernel<<<(4 * DD * DD) / 256, 256>>>(
            ffn2_w + (size_t)l * 4 * DD * DD, pwh, pwl, 4 * DD, DD);
        gemm_bf16_kernel<2><<<dim3(2, ROWS / 128), 256, GB_SMEM>>>(
            pa2h, pa2l, pwh, pwl, ffn2_b + l * DD, px,
            (__nv_bfloat16*)nullptr, (__nv_bfloat16*)nullptr,
            ROWS, DD, 4 * DD);
    }

    ln_kernel<<<ROWS, 256>>>(px, lnf_w, lnf_b, pxn);
    qscore_kernel<<<dim3(TT / 64, BB), 256>>>(pxn, queries, qattn);
    softmax2048_kernel<<<BB * QQ, 256>>>(qattn);
    selbits_kernel<<<BB * 16, 256>>>(qattn, pxn, outp_w, outp_b, pairs);
    scan_kernel<<<BB, 64>>>(pairs, mlp_w1, mlp_b1, mlp_w2, mlp_b2,
                            mlp_w3, mlp_b3, sum_all);
}

// round 14
// speedup vs baseline: 1.4389x; 1.2164x over previous
#include <cuda_runtime.h>
#include <cuda_bf16.h>
#include <math.h>
#include <stdint.h>

// ---------------------------------------------------------------------------
// Model dims (compile-time)
// ---------------------------------------------------------------------------
#define BB 4
#define TT 2048
#define DD 256
#define HH 4
#define HD 64
#define LL 2
#define QQ 128          // MAX_BITS*2 out queries

// ---------------------------------------------------------------------------
// Scratch (device globals; no runtime allocation allowed)
// ---------------------------------------------------------------------------
__device__ float g_x  [BB*TT*DD];        // residual stream
__device__ float g_xn [BB*TT*DD];        // final layernormed activations
__device__ float g_qkv[BB*TT*3*DD];      // qkv projections
__device__ __nv_bfloat16 g_a1h[BB*TT*DD],   g_a1l[BB*TT*DD];     // act split (D)
__device__ __nv_bfloat16 g_a2h[BB*TT*4*DD], g_a2l[BB*TT*4*DD];   // ffn hidden split
__device__ __nv_bfloat16 g_wth[4*DD*DD],    g_wtl[4*DD*DD];      // weight^T split

// ---------------------------------------------------------------------------
// bf16 split helpers + mma + cp.async
// ---------------------------------------------------------------------------
__device__ __forceinline__ void mma_bf16(float* c, const uint32_t* a,
                                         const uint32_t* b) {
    asm volatile(
        "mma.sync.aligned.m16n8k16.row.col.f32.bf16.bf16.f32 "
        "{%0,%1,%2,%3}, {%4,%5,%6,%7}, {%8,%9}, {%0,%1,%2,%3};"
        : "+f"(c[0]), "+f"(c[1]), "+f"(c[2]), "+f"(c[3])
        : "r"(a[0]), "r"(a[1]), "r"(a[2]), "r"(a[3]), "r"(b[0]), "r"(b[1]));
}

__device__ __forceinline__ uint32_t pack2bf(__nv_bfloat16 a, __nv_bfloat16 b) {
    return (uint32_t)__bfloat16_as_ushort(a) |
           ((uint32_t)__bfloat16_as_ushort(b) << 16);
}

__device__ __forceinline__ void split2(float x0, float x1,
                                       uint32_t& h, uint32_t& l) {
    __nv_bfloat16 h0 = __float2bfloat16(x0);
    __nv_bfloat16 h1 = __float2bfloat16(x1);
    __nv_bfloat16 l0 = __float2bfloat16(x0 - __bfloat162float(h0));
    __nv_bfloat16 l1 = __float2bfloat16(x1 - __bfloat162float(h1));
    h = pack2bf(h0, h1);
    l = pack2bf(l0, l1);
}

__device__ __forceinline__ uint32_t smem_u32(const void* p) {
    uint32_t a;
    asm("{ .reg .u64 t; cvta.to.shared.u64 t, %1; cvt.u32.u64 %0, t; }"
        : "=r"(a) : "l"(p));
    return a;
}

__device__ __forceinline__ void cpa16(uint32_t s, const void* g) {
    asm volatile("cp.async.cg.shared.global [%0], [%1], 16;"
                 :: "r"(s), "l"(g));
}
#define CPA_COMMIT() asm volatile("cp.async.commit_group;" ::: "memory")
#define CPA_WAIT0()  asm volatile("cp.async.wait_group 0;" ::: "memory")

// ---------------------------------------------------------------------------
// Reductions
// ---------------------------------------------------------------------------
__device__ __forceinline__ float blockReduceSum256(float v) {
    __shared__ float sh[8];
    int lane = threadIdx.x & 31, wid = threadIdx.x >> 5;
    #pragma unroll
    for (int o = 16; o; o >>= 1) v += __shfl_xor_sync(0xffffffffu, v, o);
    if (lane == 0) sh[wid] = v;
    __syncthreads();
    if (wid == 0) {
        float r = (lane < 8) ? sh[lane] : 0.f;
        #pragma unroll
        for (int o = 4; o; o >>= 1) r += __shfl_xor_sync(0xffffffffu, r, o);
        if (lane == 0) sh[0] = r;
    }
    __syncthreads();
    float r = sh[0];
    __syncthreads();
    return r;
}

__device__ __forceinline__ float blockReduceMax256(float v) {
    __shared__ float sh[8];
    int lane = threadIdx.x & 31, wid = threadIdx.x >> 5;
    #pragma unroll
    for (int o = 16; o; o >>= 1) v = fmaxf(v, __shfl_xor_sync(0xffffffffu, v, o));
    if (lane == 0) sh[wid] = v;
    __syncthreads();
    if (wid == 0) {
        float r = (lane < 8) ? sh[lane] : -1e30f;
        #pragma unroll
        for (int o = 4; o; o >>= 1) r = fmaxf(r, __shfl_xor_sync(0xffffffffu, r, o));
        if (lane == 0) sh[0] = r;
    }
    __syncthreads();
    float r = sh[0];
    __syncthreads();
    return r;
}

// ---------------------------------------------------------------------------
// Embedding lookup
// ---------------------------------------------------------------------------
__global__ void embed_kernel(const int* __restrict__ tokens,
                             const float* __restrict__ embed,
                             float* __restrict__ x) {
    int row = blockIdx.x;
    int d   = threadIdx.x;
    int tok = tokens[row];
    x[(size_t)row * DD + d] = embed[(size_t)tok * DD + d];
}

// ---------------------------------------------------------------------------
// LayerNorm over D=256 -> fp32
// ---------------------------------------------------------------------------
__global__ void ln_kernel(const float* __restrict__ x,
                          const float* __restrict__ w,
                          const float* __restrict__ b,
                          float* __restrict__ y) {
    int row = blockIdx.x;
    int d   = threadIdx.x;
    float v  = x[(size_t)row * DD + d];
    float mu = blockReduceSum256(v) * (1.f / DD);
    float dv = v - mu;
    float var = blockReduceSum256(dv * dv) * (1.f / DD);
    float r = rsqrtf(var + 1e-5f);
    y[(size_t)row * DD + d] = dv * r * w[d] + b[d];
}

// ---------------------------------------------------------------------------
// LayerNorm -> bf16 hi/lo split
// ---------------------------------------------------------------------------
__global__ void ln_split_kernel(const float* __restrict__ x,
                                const float* __restrict__ w,
                                const float* __restrict__ b,
                                __nv_bfloat16* __restrict__ oh,
                                __nv_bfloat16* __restrict__ ol) {
    int row = blockIdx.x;
    int d   = threadIdx.x;
    float v  = x[(size_t)row * DD + d];
    float mu = blockReduceSum256(v) * (1.f / DD);
    float dv = v - mu;
    float var = blockReduceSum256(dv * dv) * (1.f / DD);
    float r = rsqrtf(var + 1e-5f);
    float y = dv * r * w[d] + b[d];
    __nv_bfloat16 h = __float2bfloat16(y);
    size_t i = (size_t)row * DD + d;
    oh[i] = h;
    ol[i] = __float2bfloat16(y - __bfloat162float(h));
}

// ---------------------------------------------------------------------------
// Weight split + transpose: W[K][N] fp32 -> T[N][K] bf16 hi/lo
// ---------------------------------------------------------------------------
__global__ void wsplitT_kernel(const float* __restrict__ W,
                               __nv_bfloat16* __restrict__ Th,
                               __nv_bfloat16* __restrict__ Tl,
                               int K, int N) {
    int idx = blockIdx.x * 256 + threadIdx.x;   // n*K + k
    int n = idx / K, k = idx - n * K;
    float v = W[(size_t)k * N + n];
    __nv_bfloat16 h = __float2bfloat16(v);
    Th[idx] = h;
    Tl[idx] = __float2bfloat16(v - __bfloat162float(h));
}

// ---------------------------------------------------------------------------
// Pre-split bf16 HMMA GEMM, cp.async 2-stage (R11-validated shape).
// CTA 128x128, 8 warps (2x4), warp 64x32, BK=32, smem stride 40.
// ---------------------------------------------------------------------------
#define TST 40
#define STAGE_ELEMS (4 * 128 * TST)
#define GB_SMEM (2 * STAGE_ELEMS * 2)

template <int EPI>
__global__ __launch_bounds__(256, 2) void gemm_bf16_kernel(
    const __nv_bfloat16* __restrict__ Ahg, const __nv_bfloat16* __restrict__ Alg,
    const __nv_bfloat16* __restrict__ Bhg, const __nv_bfloat16* __restrict__ Blg,
    const float* __restrict__ bias, float* __restrict__ C,
    __nv_bfloat16* __restrict__ Chi, __nv_bfloat16* __restrict__ Clo,
    int M, int N, int K) {
    extern __shared__ __nv_bfloat16 smb[];
    const uint32_t sbase = smem_u32(smb);

    const int tid  = threadIdx.x;
    const int warp = tid >> 5, lane = tid & 31;
    const int g = lane >> 2, tig = lane & 3;
    const int wm = (warp & 1) * 64, wn = (warp >> 1) * 32;
    const int bm = blockIdx.y * 128, bn = blockIdx.x * 128;

    float acc[4][4][4];
    #pragma unroll
    for (int mf = 0; mf < 4; mf++)
        #pragma unroll
        for (int nf = 0; nf < 4; nf++)
            #pragma unroll
            for (int c = 0; c < 4; c++) acc[mf][nf][c] = 0.f;

    const int ar = tid >> 1, aks = (tid & 1) * 16;
    const uint32_t soA = ar * TST + aks;

    auto issue = [&](int st, int k0) {
        uint32_t sb = sbase + (uint32_t)(st * STAGE_ELEMS) * 2;
        const __nv_bfloat16* ga_h = Ahg + (size_t)(bm + ar) * K + k0 + aks;
        const __nv_bfloat16* ga_l = Alg + (size_t)(bm + ar) * K + k0 + aks;
        const __nv_bfloat16* gb_h = Bhg + (size_t)(bn + ar) * K + k0 + aks;
        const __nv_bfloat16* gb_l = Blg + (size_t)(bn + ar) * K + k0 + aks;
        cpa16(sb + (soA) * 2,                        ga_h);
        cpa16(sb + (soA + 8) * 2,                    ga_h + 8);
        cpa16(sb + (128 * TST + soA) * 2,            ga_l);
        cpa16(sb + (128 * TST + soA + 8) * 2,        ga_l + 8);
        cpa16(sb + (2 * 128 * TST + soA) * 2,        gb_h);
        cpa16(sb + (2 * 128 * TST + soA + 8) * 2,    gb_h + 8);
        cpa16(sb + (3 * 128 * TST + soA) * 2,        gb_l);
        cpa16(sb + (3 * 128 * TST + soA + 8) * 2,    gb_l + 8);
        CPA_COMMIT();
    };

    const int NT = K >> 5;
    issue(0, 0);

    for (int kt = 0; kt < NT; kt++) {
        CPA_WAIT0();
        __syncthreads();
        if (kt + 1 < NT) issue((kt + 1) & 1, (kt + 1) * 32);

        const __nv_bfloat16* Ah = smb + (kt & 1) * STAGE_ELEMS;
        const __nv_bfloat16* Al = Ah + 128 * TST;
        const __nv_bfloat16* Bh = Al + 128 * TST;
        const __nv_bfloat16* Bl = Bh + 128 * TST;

        #pragma unroll
        for (int ks2 = 0; ks2 < 2; ks2++) {
            const int kb = ks2 * 16;
            uint32_t bhf[4][2], blf[4][2];
            #pragma unroll
            for (int nf = 0; nf < 4; nf++) {
                int n0 = wn + nf * 8 + g;
                uint32_t o0 = n0 * TST + kb + tig * 2;
                bhf[nf][0] = *(const uint32_t*)&Bh[o0];
                bhf[nf][1] = *(const uint32_t*)&Bh[o0 + 8];
                blf[nf][0] = *(const uint32_t*)&Bl[o0];
                blf[nf][1] = *(const uint32_t*)&Bl[o0 + 8];
            }
            #pragma unroll
            for (int mf = 0; mf < 4; mf++) {
                int r0 = wm + mf * 16 + g;
                uint32_t oa = r0 * TST + kb + tig * 2;
                uint32_t ob = (r0 + 8) * TST + kb + tig * 2;
                uint32_t ahf[4], alf[4];
                ahf[0] = *(const uint32_t*)&Ah[oa];
                ahf[1] = *(const uint32_t*)&Ah[ob];
                ahf[2] = *(const uint32_t*)&Ah[oa + 8];
                ahf[3] = *(const uint32_t*)&Ah[ob + 8];
                alf[0] = *(const uint32_t*)&Al[oa];
                alf[1] = *(const uint32_t*)&Al[ob];
                alf[2] = *(const uint32_t*)&Al[oa + 8];
                alf[3] = *(const uint32_t*)&Al[ob + 8];
                #pragma unroll
                for (int nf = 0; nf < 4; nf++) {
                    mma_bf16(acc[mf][nf], ahf, bhf[nf]);
                    mma_bf16(acc[mf][nf], ahf, blf[nf]);
                    mma_bf16(acc[mf][nf], alf, bhf[nf]);
                }
            }
        }
    }

    #pragma unroll
    for (int mf = 0; mf < 4; mf++) {
        #pragma unroll
        for (int nf = 0; nf < 4; nf++) {
            float* cc = acc[mf][nf];
            int r0 = bm + wm + mf * 16 + g;
            int c0 = bn + wn + nf * 8 + tig * 2;
            float bv0 = bias[c0], bv1 = bias[c0 + 1];
            float v0 = cc[0] + bv0, v1 = cc[1] + bv1;
            float v2 = cc[2] + bv0, v3 = cc[3] + bv1;
            if (EPI == 1) {
                v0 = 0.5f * v0 * (1.f + erff(v0 * 0.70710678118654752f));
                v1 = 0.5f * v1 * (1.f + erff(v1 * 0.70710678118654752f));
                v2 = 0.5f * v2 * (1.f + erff(v2 * 0.70710678118654752f));
                v3 = 0.5f * v3 * (1.f + erff(v3 * 0.70710678118654752f));
                uint32_t h, l;
                split2(v0, v1, h, l);
                *(uint32_t*)(Chi + (size_t)r0 * N + c0) = h;
                *(uint32_t*)(Clo + (size_t)r0 * N + c0) = l;
                split2(v2, v3, h, l);
                *(uint32_t*)(Chi + (size_t)(r0 + 8) * N + c0) = h;
                *(uint32_t*)(Clo + (size_t)(r0 + 8) * N + c0) = l;
            } else {
                if (EPI == 2) {
                    float2 o0 = *(const float2*)(C + (size_t)r0 * N + c0);
                    float2 o1 = *(const float2*)(C + (size_t)(r0 + 8) * N + c0);
                    v0 += o0.x; v1 += o0.y; v2 += o1.x; v3 += o1.y;
                }
                float2 s0; s0.x = v0; s0.y = v1;
                float2 s1; s1.x = v2; s1.y = v3;
                *(float2*)(C + (size_t)r0 * N + c0)       = s0;
                *(float2*)(C + (size_t)(r0 + 8) * N + c0) = s1;
            }
        }
    }
}

// ---------------------------------------------------------------------------
// RoPE applied in-place to q and k parts of g_qkv.
// ---------------------------------------------------------------------------
__global__ void rope_kernel(float* __restrict__ qkv) {
    int idx  = blockIdx.x * blockDim.x + threadIdx.x;
    int d    = idx & 31;
    int h    = (idx >> 5) & 3;
    int part = (idx >> 7) & 1;
    int row  = idx >> 8;           // b*T + t
    int t    = row & (TT - 1);
    float inv = powf(10000.f, -(float)d * (1.f / 32.f));
    float ang = (float)t * inv;
    float s, c;
    sincosf(ang, &s, &c);
    float* p = qkv + (size_t)row * (3 * DD) + part * DD + h * HD;
    float x0 = p[d], x1 = p[d + 32];
    p[d]      = x0 * c - x1 * s;
    p[d + 32] = x1 * c + x0 * s;
}

// ---------------------------------------------------------------------------
// Full-HMMA flash attention: bf16 QK^T + frag softmax + split-bf16 PV.
// One block per (b, h, 64-q tile), 128 threads = 4 warps.
// Warp w owns query rows 16w..16w+15. All state in fragment layout:
// softmax corr and 1/l applied locally in the warp quad (no smem round-trip).
// V staged transposed hi/lo [d][s] (R9-validated); P split in registers
// (R9-validated C-frag->A-frag identity). Epilogue writes bf16 hi/lo.
// ---------------------------------------------------------------------------
#define FST 72
#define FATTN_SMEM (4 * 64 * FST * 2)

__global__ __launch_bounds__(128) void fattn_kernel(
    const float* __restrict__ qkv,
    __nv_bfloat16* __restrict__ oh, __nv_bfloat16* __restrict__ ol) {
    extern __shared__ __nv_bfloat16 fsm[];
    __nv_bfloat16* Qb  = fsm;                // [q][hd]
    __nv_bfloat16* Kb  = Qb  + 64 * FST;     // [s][hd]
    __nv_bfloat16* Vth = Kb  + 64 * FST;     // [d][s] hi
    __nv_bfloat16* Vtl = Vth + 64 * FST;     // [d][s] lo

    const int qt = (gridDim.x - 1) - blockIdx.x;
    const int h  = blockIdx.y;
    const int b  = blockIdx.z;
    const int tid = threadIdx.x;
    const int warp = tid >> 5, lane = tid & 31;
    const int g = lane >> 2, tig = lane & 3;
    const int wm16 = warp * 16;
    const int r0 = wm16 + g, r1 = r0 + 8;

    const int lr = tid >> 1;          // 0..63
    const int lc = (tid & 1) * 32;    // 0 or 32

    const float* base = qkv + (size_t)b * TT * (3 * DD);

    // ---- stage Q (scaled, plain bf16) ----
    {
        const float* qrow = base + (size_t)(qt * 64 + lr) * (3 * DD) + h * HD + lc;
        #pragma unroll
        for (int m = 0; m < 8; m++) {
            float4 v = *(const float4*)(qrow + m * 4);
            uint32_t p0 = pack2bf(__float2bfloat16(v.x * 0.125f),
                                  __float2bfloat16(v.y * 0.125f));
            uint32_t p1 = pack2bf(__float2bfloat16(v.z * 0.125f),
                                  __float2bfloat16(v.w * 0.125f));
            uint32_t off = lr * FST + lc + m * 4;
            *(uint32_t*)&Qb[off]     = p0;
            *(uint32_t*)&Qb[off + 2] = p1;
        }
    }

    float m0 = -1e30f, m1 = -1e30f, l0s = 0.f, l1s = 0.f;
    float of[8][4];
    #pragma unroll
    for (int j = 0; j < 8; j++)
        #pragma unroll
        for (int c = 0; c < 4; c++) of[j][c] = 0.f;

    for (int kt = 0; kt <= qt; kt++) {
        __syncthreads();   // prev tile's MMAs done reading Kb/Vt (Q staged, 1st)
        // ---- stage K (plain bf16) + V transposed hi/lo ----
        {
            const float* krow = base + (size_t)(kt * 64 + lr) * (3 * DD) + DD + h * HD + lc;
            #pragma unroll
            for (int m = 0; m < 8; m++) {
                float4 v = *(const float4*)(krow + m * 4);
                uint32_t p0 = pack2bf(__float2bfloat16(v.x), __float2bfloat16(v.y));
                uint32_t p1 = pack2bf(__float2bfloat16(v.z), __float2bfloat16(v.w));
                uint32_t off = lr * FST + lc + m * 4;
                *(uint32_t*)&Kb[off]     = p0;
                *(uint32_t*)&Kb[off + 2] = p1;
            }
            const float* vrow = base + (size_t)(kt * 64 + lr) * (3 * DD) + 2 * DD + h * HD + lc;
            #pragma unroll
            for (int q = 0; q < 32; q++) {
                float v = vrow[q];
                int d = lc + q;
                __nv_bfloat16 vh = __float2bfloat16(v);
                Vth[d * FST + lr] = vh;
                Vtl[d * FST + lr] = __float2bfloat16(v - __bfloat162float(vh));
            }
        }
        __syncthreads();

        // ---- S = Q K^T via HMMA (warp rows wm16..+15, 64 s-cols) ----
        float sf[8][4];
        #pragma unroll
        for (int j = 0; j < 8; j++)
            #pragma unroll
            for (int c = 0; c < 4; c++) sf[j][c] = 0.f;

        #pragma unroll
        for (int ks = 0; ks < 4; ks++) {
            uint32_t oa = r0 * FST + ks * 16 + tig * 2;
            uint32_t ob = r1 * FST + ks * 16 + tig * 2;
            uint32_t qa[4];
            qa[0] = *(const uint32_t*)&Qb[oa];
            qa[1] = *(const uint32_t*)&Qb[ob];
            qa[2] = *(const uint32_t*)&Qb[oa + 8];
            qa[3] = *(const uint32_t*)&Qb[ob + 8];
            #pragma unroll
            for (int j = 0; j < 8; j++) {
                int n0 = j * 8 + g;
                uint32_t okb = n0 * FST + ks * 16 + tig * 2;
                uint32_t bh[2];
                bh[0] = *(const uint32_t*)&Kb[okb];
                bh[1] = *(const uint32_t*)&Kb[okb + 8];
                mma_bf16(sf[j], qa, bh);
            }
        }

        // ---- causal mask on diagonal tile ----
        if (kt == qt) {
            #pragma unroll
            for (int j = 0; j < 8; j++) {
                int c0 = j * 8 + tig * 2;
                if (c0     > r0) sf[j][0] = -1e30f;
                if (c0 + 1 > r0) sf[j][1] = -1e30f;
                if (c0     > r1) sf[j][2] = -1e30f;
                if (c0 + 1 > r1) sf[j][3] = -1e30f;
            }
        }

        // ---- online softmax in frag layout (quad reduce over tig) ----
        float rm0 = -1e30f, rm1 = -1e30f;
        #pragma unroll
        for (int j = 0; j < 8; j++) {
            rm0 = fmaxf(rm0, fmaxf(sf[j][0], sf[j][1]));
            rm1 = fmaxf(rm1, fmaxf(sf[j][2], sf[j][3]));
        }
        rm0 = fmaxf(rm0, __shfl_xor_sync(0xffffffffu, rm0, 1));
        rm0 = fmaxf(rm0, __shfl_xor_sync(0xffffffffu, rm0, 2));
        rm1 = fmaxf(rm1, __shfl_xor_sync(0xffffffffu, rm1, 1));
        rm1 = fmaxf(rm1, __shfl_xor_sync(0xffffffffu, rm1, 2));
        float nm0 = fmaxf(m0, rm0), nm1 = fmaxf(m1, rm1);
        float cr0 = __expf(m0 - nm0), cr1 = __expf(m1 - nm1);
        m0 = nm0; m1 = nm1;
        float rs0 = 0.f, rs1 = 0.f;
        #pragma unroll
        for (int j = 0; j < 8; j++) {
            sf[j][0] = __expf(sf[j][0] - nm0);
            sf[j][1] = __expf(sf[j][1] - nm0);
            sf[j][2] = __expf(sf[j][2] - nm1);
            sf[j][3] = __expf(sf[j][3] - nm1);
            rs0 += sf[j][0] + sf[j][1];
            rs1 += sf[j][2] + sf[j][3];
        }
        rs0 += __shfl_xor_sync(0xffffffffu, rs0, 1);
        rs0 += __shfl_xor_sync(0xffffffffu, rs0, 2);
        rs1 += __shfl_xor_sync(0xffffffffu, rs1, 1);
        rs1 += __shfl_xor_sync(0xffffffffu, rs1, 2);
        l0s = l0s * cr0 + rs0;
        l1s = l1s * cr1 + rs1;
        #pragma unroll
        for (int j = 0; j < 8; j++) {
            of[j][0] *= cr0; of[j][1] *= cr0;
            of[j][2] *= cr1; of[j][3] *= cr1;
        }

        // ---- O += P V (P split in registers, 3-term HMMA) ----
        #pragma unroll
        for (int p = 0; p < 4; p++) {
            int j0 = 2 * p, j1 = 2 * p + 1;
            uint32_t pah[4], pal[4];
            split2(sf[j0][0], sf[j0][1], pah[0], pal[0]);
            split2(sf[j0][2], sf[j0][3], pah[1], pal[1]);
            split2(sf[j1][0], sf[j1][1], pah[2], pal[2]);
            split2(sf[j1][2], sf[j1][3], pah[3], pal[3]);
            #pragma unroll
            for (int j = 0; j < 8; j++) {
                int n0 = j * 8 + g;
                uint32_t okb = n0 * FST + p * 16 + tig * 2;
                uint32_t bh[2], bl[2];
                bh[0] = *(const uint32_t*)&Vth[okb];
                bh[1] = *(const uint32_t*)&Vth[okb + 8];
                bl[0] = *(const uint32_t*)&Vtl[okb];
                bl[1] = *(const uint32_t*)&Vtl[okb + 8];
                mma_bf16(of[j], pah, bh);
                mma_bf16(of[j], pah, bl);
                mma_bf16(of[j], pal, bh);
            }
        }
    }

    // ---- epilogue: normalize + bf16 hi/lo split ----
    {
        float inv0 = 1.f / l0s, inv1 = 1.f / l1s;
        int t0 = qt * 64 + r0;
        int t1 = t0 + 8;
        #pragma unroll
        for (int j = 0; j < 8; j++) {
            int col = j * 8 + tig * 2;
            uint32_t h0, l0, h1, l1;
            split2(of[j][0] * inv0, of[j][1] * inv0, h0, l0);
            split2(of[j][2] * inv1, of[j][3] * inv1, h1, l1);
            size_t i0 = (size_t)(b * TT + t0) * DD + h * HD + col;
            size_t i1 = (size_t)(b * TT + t1) * DD + h * HD + col;
            *(uint32_t*)(oh + i0) = h0;
            *(uint32_t*)(ol + i0) = l0;
            *(uint32_t*)(oh + i1) = h1;
            *(uint32_t*)(ol + i1) = l1;
        }
    }
}

// ---------------------------------------------------------------------------
// q_scores as GEMM: C[q,t] = (1/16) * queries[q,:].xn[b,t,:]
// ---------------------------------------------------------------------------
__global__ __launch_bounds__(256) void qscore_kernel(
    const float* __restrict__ xn, const float* __restrict__ queries,
    float* __restrict__ qattn) {
    __shared__ float Qs[2][8][128];
    __shared__ float Xs[2][8][64];
    int b  = blockIdx.y;
    int t0 = blockIdx.x * 64;
    int tid = threadIdx.x;
    int tx = tid & 15, ty = tid >> 4;

    int qr = tid >> 1, qc = (tid & 1) * 4;
    int xr = tid >> 1, xc = (tid & 1) * 4;
    bool xact = tid < 128;
    const float* xb = xn + (size_t)b * TT * DD;

    float acc[8][4];
    #pragma unroll
    for (int i = 0; i < 8; i++)
        #pragma unroll
        for (int j = 0; j < 4; j++) acc[i][j] = 0.f;

    {
        float4 qv = *(const float4*)(queries + qr * DD + qc);
        Qs[0][qc + 0][qr] = qv.x; Qs[0][qc + 1][qr] = qv.y;
        Qs[0][qc + 2][qr] = qv.z; Qs[0][qc + 3][qr] = qv.w;
        if (xact) {
            float4 xv = *(const float4*)(xb + (size_t)(t0 + xr) * DD + xc);
            Xs[0][xc + 0][xr] = xv.x; Xs[0][xc + 1][xr] = xv.y;
            Xs[0][xc + 2][xr] = xv.z; Xs[0][xc + 3][xr] = xv.w;
        }
    }
    __syncthreads();

    const int NT = DD >> 3;   // 32
    for (int kt = 0; kt < NT; kt++) {
        int cur = kt & 1;
        float4 qv, xv;
        if (kt + 1 < NT) {
            qv = *(const float4*)(queries + qr * DD + (kt + 1) * 8 + qc);
            if (xact)
                xv = *(const float4*)(xb + (size_t)(t0 + xr) * DD + (kt + 1) * 8 + xc);
        }
        #pragma unroll
        for (int kk = 0; kk < 8; kk++) {
            float a0[8], b0[4];
            *(float4*)&a0[0] = *(const float4*)&Qs[cur][kk][ty * 4];
            *(float4*)&a0[4] = *(const float4*)&Qs[cur][kk][64 + ty * 4];
            *(float4*)&b0[0] = *(const float4*)&Xs[cur][kk][tx * 4];
            #pragma unroll
            for (int i = 0; i < 8; i++)
                #pragma unroll
                for (int j = 0; j < 4; j++)
                    acc[i][j] += a0[i] * b0[j];
        }
        if (kt + 1 < NT) {
            int nxt = cur ^ 1;
            Qs[nxt][qc + 0][qr] = qv.x; Qs[nxt][qc + 1][qr] = qv.y;
            Qs[nxt][qc + 2][qr] = qv.z; Qs[nxt][qc + 3][qr] = qv.w;
            if (xact) {
                Xs[nxt][xc + 0][xr] = xv.x; Xs[nxt][xc + 1][xr] = xv.y;
                Xs[nxt][xc + 2][xr] = xv.z; Xs[nxt][xc + 3][xr] = xv.w;
            }
            __syncthreads();
        }
    }

    #pragma unroll
    for (int i = 0; i < 8; i++) {
        int q = (i < 4) ? ty * 4 + i : 64 + ty * 4 + (i - 4);
        float4 o;
        o.x = acc[i][0] * 0.0625f; o.y = acc[i][1] * 0.0625f;
        o.z = acc[i][2] * 0.0625f; o.w = acc[i][3] * 0.0625f;
        *(float4*)(qattn + (size_t)(b * QQ + q) * TT + t0 + tx * 4) = o;
    }
}

// ---------------------------------------------------------------------------
// Softmax over last dim (2048), in place. One block per row.
// ---------------------------------------------------------------------------
__global__ __launch_bounds__(256) void softmax2048_kernel(float* __restrict__ p) {
    float* row = p + (size_t)blockIdx.x * TT;
    int tid = threadIdx.x;
    float v[8];
    float mx = -1e30f;
    #pragma unroll
    for (int j = 0; j < 8; j++) { v[j] = row[tid + 256 * j]; mx = fmaxf(mx, v[j]); }
    mx = blockReduceMax256(mx);
    float s = 0.f;
    #pragma unroll
    for (int j = 0; j < 8; j++) { v[j] = __expf(v[j] - mx); s += v[j]; }
    s = blockReduceSum256(s);
    float inv = 1.f / s;
    #pragma unroll
    for (int j = 0; j < 8; j++) row[tid + 256 * j] = v[j] * inv;
}

// ---------------------------------------------------------------------------
// selbits: 8 query rows per block share one streaming pass over xn[b].
// ---------------------------------------------------------------------------
__global__ __launch_bounds__(256) void selbits_kernel(
    const float* __restrict__ qattn, const float* __restrict__ xn,
    const float* __restrict__ outp_w, const float* __restrict__ outp_b,
    float* __restrict__ pairs) {
    int b  = blockIdx.x >> 4;
    int qg = blockIdx.x & 15;
    int d  = threadIdx.x;
    __shared__ float ws[8][64];
    float acc[8] = {};
    const float* xb = xn + (size_t)b * TT * DD;
    int g  = threadIdx.x >> 5;
    int tt = threadIdx.x & 31;
    const float* wbase = qattn + (size_t)(b * QQ + qg * 8 + g) * TT;

    for (int t0 = 0; t0 < TT; t0 += 64) {
        ws[g][tt]      = wbase[t0 + tt];
        ws[g][tt + 32] = wbase[t0 + tt + 32];
        __syncthreads();
        #pragma unroll 8
        for (int t = 0; t < 64; t++) {
            float x = xb[(size_t)(t0 + t) * DD + d];
            #pragma unroll
            for (int g2 = 0; g2 < 8; g2++) acc[g2] += ws[g2][t] * x;
        }
        __syncthreads();
    }

    float wd = outp_w[d];
    #pragma unroll
    for (int g2 = 0; g2 < 8; g2++) {
        float s = blockReduceSum256(acc[g2] * wd);
        if (d == 0)
            pairs[b * QQ + qg * 8 + g2] =
                1.f / (1.f + __expf(-(s + outp_b[0])));
    }
}

// ---------------------------------------------------------------------------
// 64-step recurrent MLP scan. One block per batch row, 64 threads.
// ---------------------------------------------------------------------------
__global__ __launch_bounds__(64) void scan_kernel(
    const float* __restrict__ pairs,
    const float* __restrict__ w1, const float* __restrict__ b1,
    const float* __restrict__ w2, const float* __restrict__ b2,
    const float* __restrict__ w3, const float* __restrict__ b3,
    float* __restrict__ sum_all) {
    int b = blockIdx.x;
    int j = threadIdx.x;
    __shared__ float h1[64], h2[64];
    __shared__ float carry;
    if (j == 0) carry = 0.f;

    float w1a = w1[j], w1b = w1[64 + j], w1c = w1[128 + j], bb1 = b1[j];
    float w2c[64];
    #pragma unroll
    for (int k = 0; k < 64; k++) w2c[k] = w2[k * 64 + j];
    float bb2 = b2[j];
    __syncthreads();

    for (int i = 0; i < 64; i++) {
        float z0 = pairs[b * QQ + i * 2];
        float z1 = pairs[b * QQ + i * 2 + 1];
        float z2 = carry;
        h1[j] = fmaxf(0.f, z0 * w1a + z1 * w1b + z2 * w1c + bb1);
        __syncthreads();
        float acc = bb2;
        #pragma unroll
        for (int k = 0; k < 64; k++) acc += h1[k] * w2c[k];
        h2[j] = fmaxf(0.f, acc);
        __syncthreads();
        if (j == 0) {
            float o0 = b3[0], o1 = b3[1];
            #pragma unroll
            for (int k = 0; k < 64; k++) {
                o0 += h2[k] * w3[k * 2];
                o1 += h2[k] * w3[k * 2 + 1];
            }
            o0 = 1.f / (1.f + __expf(-o0));
            o1 = 1.f / (1.f + __expf(-o1));
            sum_all[b * 65 + i] = o0;
            carry = o1;
        }
        __syncthreads();
    }
    if (j == 0) sum_all[b * 65 + 64] = carry;
}

// ---------------------------------------------------------------------------
// Launch
// ---------------------------------------------------------------------------
extern "C" void kernel_launch(void* const* d_in, const int* in_sizes, int n_in,
                              void* d_out, int out_size) {
    const int*   tokens   = (const int*)  d_in[0];
    const float* embed    = (const float*)d_in[1];
    const float* ln1_w    = (const float*)d_in[2];
    const float* ln1_b    = (const float*)d_in[3];
    const float* qkv_w    = (const float*)d_in[4];
    const float* qkv_b    = (const float*)d_in[5];
    const float* proj_w   = (const float*)d_in[6];
    const float* proj_b   = (const float*)d_in[7];
    const float* ln2_w    = (const float*)d_in[8];
    const float* ln2_b    = (const float*)d_in[9];
    const float* ffn1_w   = (const float*)d_in[10];
    const float* ffn1_b   = (const float*)d_in[11];
    const float* ffn2_w   = (const float*)d_in[12];
    const float* ffn2_b   = (const float*)d_in[13];
    const float* lnf_w    = (const float*)d_in[14];
    const float* lnf_b    = (const float*)d_in[15];
    const float* queries  = (const float*)d_in[16];
    const float* outp_w   = (const float*)d_in[17];
    const float* outp_b   = (const float*)d_in[18];
    const float* mlp_w1   = (const float*)d_in[19];
    const float* mlp_b1   = (const float*)d_in[20];
    const float* mlp_w2   = (const float*)d_in[21];
    const float* mlp_b2   = (const float*)d_in[22];
    const float* mlp_w3   = (const float*)d_in[23];
    const float* mlp_b3   = (const float*)d_in[24];

    float* out     = (float*)d_out;
    float* sum_all = out;                  // (B,65)   = 260
    float* pairs   = out + 260;            // (B,64,2) = 512
    float* qattn   = out + 772;            // (B,128,2048)

    float *px, *pxn, *pqkv;
    __nv_bfloat16 *pa1h, *pa1l, *pa2h, *pa2l, *pwh, *pwl;
    cudaGetSymbolAddress((void**)&px,   g_x);
    cudaGetSymbolAddress((void**)&pxn,  g_xn);
    cudaGetSymbolAddress((void**)&pqkv, g_qkv);
    cudaGetSymbolAddress((void**)&pa1h, g_a1h);
    cudaGetSymbolAddress((void**)&pa1l, g_a1l);
    cudaGetSymbolAddress((void**)&pa2h, g_a2h);
    cudaGetSymbolAddress((void**)&pa2l, g_a2l);
    cudaGetSymbolAddress((void**)&pwh,  g_wth);
    cudaGetSymbolAddress((void**)&pwl,  g_wtl);

    cudaFuncSetAttribute(fattn_kernel,
                         cudaFuncAttributeMaxDynamicSharedMemorySize, FATTN_SMEM);
    cudaFuncSetAttribute(gemm_bf16_kernel<0>,
                         cudaFuncAttributeMaxDynamicSharedMemorySize, GB_SMEM);
    cudaFuncSetAttribute(gemm_bf16_kernel<1>,
                         cudaFuncAttributeMaxDynamicSharedMemorySize, GB_SMEM);
    cudaFuncSetAttribute(gemm_bf16_kernel<2>,
                         cudaFuncAttributeMaxDynamicSharedMemorySize, GB_SMEM);

    const int ROWS = BB * TT;  // 8192

    embed_kernel<<<ROWS, 256>>>(tokens, embed, px);

    for (int l = 0; l < LL; l++) {
        // ---- attention block ----
        ln_split_kernel<<<ROWS, 256>>>(px, ln1_w + l * DD, ln1_b + l * DD,
                                       pa1h, pa1l);
        wsplitT_kernel<<<(3 * DD * DD) / 256, 256>>>(
            qkv_w + (size_t)l * DD * 3 * DD, pwh, pwl, DD, 3 * DD);
        gemm_bf16_kernel<0><<<dim3(6, ROWS / 128), 256, GB_SMEM>>>(
            pa1h, pa1l, pwh, pwl, qkv_b + l * 3 * DD, pqkv,
            (__nv_bfloat16*)nullptr, (__nv_bfloat16*)nullptr,
            ROWS, 3 * DD, DD);
        rope_kernel<<<ROWS, 256>>>(pqkv);
        fattn_kernel<<<dim3(TT / 64, HH, BB), 128, FATTN_SMEM>>>(pqkv, pa1h, pa1l);
        wsplitT_kernel<<<(DD * DD) / 256, 256>>>(
            proj_w + (size_t)l * DD * DD, pwh, pwl, DD, DD);
        gemm_bf16_kernel<2><<<dim3(2, ROWS / 128), 256, GB_SMEM>>>(
            pa1h, pa1l, pwh, pwl, proj_b + l * DD, px,
            (__nv_bfloat16*)nullptr, (__nv_bfloat16*)nullptr,
            ROWS, DD, DD);
        // ---- ffn block ----
        ln_split_kernel<<<ROWS, 256>>>(px, ln2_w + l * DD, ln2_b + l * DD,
                                       pa1h, pa1l);
        wsplitT_kernel<<<(4 * DD * DD) / 256, 256>>>(
            ffn1_w + (size_t)l * DD * 4 * DD, pwh, pwl, DD, 4 * DD);
        gemm_bf16_kernel<1><<<dim3(8, ROWS / 128), 256, GB_SMEM>>>(
            pa1h, pa1l, pwh, pwl, ffn1_b + l * 4 * DD, (float*)nullptr,
            pa2h, pa2l, ROWS, 4 * DD, DD);
        wsplitT_kernel<<<(4 * DD * DD) / 256, 256>>>(
            ffn2_w + (size_t)l * 4 * DD * DD, pwh, pwl, 4 * DD, DD);
        gemm_bf16_kernel<2><<<dim3(2, ROWS / 128), 256, GB_SMEM>>>(
            pa2h, pa2l, pwh, pwl, ffn2_b + l * DD, px,
            (__nv_bfloat16*)nullptr, (__nv_bfloat16*)nullptr,
            ROWS, DD, 4 * DD);
    }

    ln_kernel<<<ROWS, 256>>>(px, lnf_w, lnf_b, pxn);
    qscore_kernel<<<dim3(TT / 64, BB), 256>>>(pxn, queries, qattn);
    softmax2048_kernel<<<BB * QQ, 256>>>(qattn);
    selbits_kernel<<<BB * 16, 256>>>(qattn, pxn, outp_w, outp_b, pairs);
    scan_kernel<<<BB, 64>>>(pairs, mlp_w1, mlp_b1, mlp_w2, mlp_b2,
                            mlp_w3, mlp_b3, sum_all);
}